// round 14
// baseline (speedup 1.0000x reference)
#include <cuda_runtime.h>
#include <cuda_fp16.h>
#include <math.h>
#include <stdint.h>

#define BB 4
#define LL 1024
#define DIMM 1024
#define NHEADS 16
#define HD 64
#define NTOK (BB*LL)
#define HID 512
#define NE 16
#define NSHARED 2048
#define NSLOTS (NTOK*2)

// ---------------- scratch ----------------
__device__ float g_qkv[NTOK*3*DIMM];
__device__ float g_h[NTOK*DIMM];
__device__ float g_xf[NTOK*DIMM];
// fp16 buffers
#define WSEG 1048576ll
__device__ __half g_wh[26*WSEG];
__device__ __half g_hn16[NTOK*DIMM];
__device__ __half g_q16[NTOK*DIMM];
__device__ __half g_k16[NTOK*DIMM];
__device__ __half g_v16[NTOK*DIMM];
__device__ __half g_a16[NTOK*DIMM];
__device__ __half g_x16[NTOK*DIMM];
__device__ __half g_ta16[NTOK*NSHARED];
__device__ __half g_e16[NSLOTS*HID];
// routing
__device__ int   g_topi[NSLOTS];
__device__ float g_topw[NSLOTS];
__device__ int   g_counts[NE];
__device__ int   g_cursor[NE];
__device__ int   g_offs[NE];
__device__ int   g_order[NSLOTS];
__device__ float g_wslot[NSLOTS];

__device__ __forceinline__ uint32_t smem_u32(const void* p){
    uint32_t a;
    asm("{ .reg .u64 t; cvta.to.shared.u64 t, %1; cvt.u32.u64 %0, t; }" : "=r"(a) : "l"(p));
    return a;
}

#define LDMX4(r0,r1,r2,r3,addr) \
    asm volatile("ldmatrix.sync.aligned.m8n8.x4.shared.b16 {%0,%1,%2,%3}, [%4];" \
        : "=r"(r0),"=r"(r1),"=r"(r2),"=r"(r3) : "r"(addr))
#define LDMX4T(r0,r1,r2,r3,addr) \
    asm volatile("ldmatrix.sync.aligned.m8n8.x4.trans.shared.b16 {%0,%1,%2,%3}, [%4];" \
        : "=r"(r0),"=r"(r1),"=r"(r2),"=r"(r3) : "r"(addr))

#define MMAH(c0,c1,c2,c3,a0,a1,a2,a3,b0,b1) \
    asm volatile("mma.sync.aligned.m16n8k16.row.col.f32.f16.f16.f32 " \
        "{%0,%1,%2,%3}, {%4,%5,%6,%7}, {%8,%9}, {%0,%1,%2,%3};" \
        : "+f"(c0),"+f"(c1),"+f"(c2),"+f"(c3) \
        : "r"(a0),"r"(a1),"r"(a2),"r"(a3), "r"(b0),"r"(b1))

#define CPASYNC(dst,src,sz) \
    asm volatile("cp.async.cg.shared.global [%0], [%1], 16, %2;" :: "r"(dst), "l"(src), "r"(sz))
#define CPCOMMIT() asm volatile("cp.async.commit_group;")
#define CPWAIT(n)  asm volatile("cp.async.wait_group %0;" :: "n"(n))

// ========== fp16 GEMM: C = A * B^T ; 128x256 tile, 64x64 warp tile, K-chunk 64 ==========
// mode: 0 fp32 out, 1 fp32 += res, 3 silu->fp16, 4 atomic MoE combine,
//       5 paired silu: cols 0-127 = a1, 128-255 = a2; out fp16 silu(a1)*a2
#define ROWB 144                    // bytes per smem row (64 halves + 8 pad)
#define STAGE_BYTES (384*ROWB)      // A 128 rows + B 256 rows
#define NSTAGE 3
#define MM16_SMEM (NSTAGE*STAGE_BYTES)

__global__ void __launch_bounds__(256,1) mm16(
    const __half* __restrict__ Ah, const __half* __restrict__ Bh,
    float* __restrict__ C, const float* __restrict__ res,
    __half* __restrict__ Cp16,
    int M, int N, int K, int lda, int ldb, int ldc, int mode,
    const int* __restrict__ counts, const int* __restrict__ offs,
    const int* __restrict__ rows,
    const int* __restrict__ omap, const float* __restrict__ wsl,
    long long bStrideE)
{
    extern __shared__ __align__(16) char dsm[];
    __shared__ int rsrc[128];
    uint32_t ub = smem_u32(dsm);
    int tid = threadIdx.x, wid = tid >> 5, lane = tid & 31;
    int e = blockIdx.z;

    int Mloc = M, rowOff = 0;
    const __half* Bp = Bh;
    if (counts){ Mloc = counts[e]; rowOff = offs[e]; Bp = Bh + (long long)e*bStrideE; }
    int m0 = blockIdx.y * 128;
    if (m0 >= Mloc) return;
    int n0 = blockIdx.x * 256;

    for (int i = tid; i < 128; i += 256){
        int gr = m0 + i;
        rsrc[i] = (gr < Mloc) ? (rows ? rows[rowOff + gr] : (counts ? rowOff + gr : gr)) : -1;
    }
    __syncthreads();

    // copy plan: each thread owns one 16B column-part (part = tid&7) of
    // 4 gathered A-rows (r0,r0+32,r0+64,r0+96) and 8 strided B-rows.
    int r0 = tid >> 3, part = tid & 7;
    uint32_t dbase = (uint32_t)(r0*ROWB + part*16);
    const __half* ap[4]; int asz[4];
    #pragma unroll
    for (int i = 0; i < 4; i++){
        int s = rsrc[r0 + 32*i];
        asz[i] = (s >= 0) ? 16 : 0;
        ap[i] = Ah + (long long)((s >= 0) ? s : 0)*lda + part*8;
    }
    const __half* bb = Bp + (long long)(n0 + r0)*ldb + part*8;
    long long str32 = 32ll*ldb;

#define MM16_ISSUE(stg, kc) do { \
    uint32_t dd = ub + (stg)*STAGE_BYTES + dbase; int ko = (kc)*64; \
    CPASYNC(dd,            ap[0]+ko, asz[0]); \
    CPASYNC(dd+32*ROWB,    ap[1]+ko, asz[1]); \
    CPASYNC(dd+64*ROWB,    ap[2]+ko, asz[2]); \
    CPASYNC(dd+96*ROWB,    ap[3]+ko, asz[3]); \
    _Pragma("unroll") \
    for (int i = 0; i < 8; i++) CPASYNC(dd+(128+32*i)*ROWB, bb + i*str32 + ko, 16); \
    CPCOMMIT(); } while(0)

    float acc[4][8][4];
    #pragma unroll
    for (int i=0;i<4;i++) for (int j=0;j<8;j++) for (int f=0;f<4;f++) acc[i][j][f]=0.f;

    int wm = (wid >> 2) * 64, wn = (wid & 3) * 64;
    int lrow = lane & 15, lsel = (lane >> 4) * 8;
    int nk = K >> 6;

    MM16_ISSUE(0, 0);
    if (nk > 1) MM16_ISSUE(1, 1);
    for (int kc = 0; kc < nk; kc++){
        if (kc + 1 < nk) CPWAIT(1); else CPWAIT(0);
        __syncthreads();
        int nxt = kc + 2;
        if (nxt < nk) MM16_ISSUE(nxt % NSTAGE, nxt);
        uint32_t us = ub + (kc % NSTAGE)*STAGE_BYTES;
        #pragma unroll
        for (int ks = 0; ks < 4; ks++){
            int kofs2 = (ks*16 + lsel)*2;
            uint32_t ah[4][4], bh[4][4];
            #pragma unroll
            for (int mt = 0; mt < 4; mt++){
                uint32_t ad = us + (uint32_t)((wm + mt*16 + lrow)*ROWB) + kofs2;
                LDMX4(ah[mt][0],ah[mt][1],ah[mt][2],ah[mt][3], ad);
            }
            #pragma unroll
            for (int j = 0; j < 4; j++){
                uint32_t bd = us + (uint32_t)((128 + wn + j*16 + lrow)*ROWB) + kofs2;
                LDMX4(bh[j][0],bh[j][1],bh[j][2],bh[j][3], bd);
            }
            #pragma unroll
            for (int mt = 0; mt < 4; mt++){
                #pragma unroll
                for (int j = 0; j < 4; j++){
                    float* c0 = acc[mt][2*j];
                    float* c1 = acc[mt][2*j+1];
                    MMAH(c0[0],c0[1],c0[2],c0[3], ah[mt][0],ah[mt][1],ah[mt][2],ah[mt][3], bh[j][0],bh[j][2]);
                    MMAH(c1[0],c1[1],c1[2],c1[3], ah[mt][0],ah[mt][1],ah[mt][2],ah[mt][3], bh[j][1],bh[j][3]);
                }
            }
        }
    }

    int rbase = lane >> 2, cbase = (lane & 3) * 2;

    if (mode == 5){
        // paired silu epilogue: a1 = cols 0..127, a2 = cols 128..255 (same out cols)
        float* stage = (float*)dsm;    // 128 x 132 fp32
        __syncthreads();               // pipeline smem dead, reuse
        if ((wid & 3) >= 2){
            int cb = wn - 128;
            #pragma unroll
            for (int mt = 0; mt < 4; mt++)
                #pragma unroll
                for (int nt = 0; nt < 8; nt++)
                    #pragma unroll
                    for (int half = 0; half < 2; half++){
                        int lm = wm + mt*16 + rbase + half*8;
                        int c = cb + nt*8 + cbase;
                        stage[lm*132 + c]   = acc[mt][nt][2*half];
                        stage[lm*132 + c+1] = acc[mt][nt][2*half+1];
                    }
        }
        __syncthreads();
        if ((wid & 3) < 2){
            int n0h = blockIdx.x * 128;
            #pragma unroll
            for (int mt = 0; mt < 4; mt++)
                #pragma unroll
                for (int nt = 0; nt < 8; nt++)
                    #pragma unroll
                    for (int half = 0; half < 2; half++){
                        int lm = wm + mt*16 + rbase + half*8;
                        int c = wn + nt*8 + cbase;
                        float a1x = acc[mt][nt][2*half];
                        float a1y = acc[mt][nt][2*half+1];
                        float a2x = stage[lm*132 + c];
                        float a2y = stage[lm*132 + c+1];
                        float ox = a1x/(1.f+expf(-a1x))*a2x;
                        float oy = a1y/(1.f+expf(-a1y))*a2y;
                        long long ci = (long long)(m0 + lm)*ldc + n0h + c;
                        *(__half2*)(Cp16 + ci) = __floats2half2_rn(ox, oy);
                    }
        }
        return;
    }

    #pragma unroll
    for (int mt = 0; mt < 4; mt++){
        #pragma unroll
        for (int nt = 0; nt < 8; nt++){
            int gn = n0 + wn + nt*8 + cbase;
            #pragma unroll
            for (int half = 0; half < 2; half++){
                int gm = m0 + wm + mt*16 + rbase + half*8;
                if (gm >= Mloc) continue;
                float v0 = acc[mt][nt][2*half];
                float v1 = acc[mt][nt][2*half+1];
                long long ci = (long long)(rowOff + gm)*ldc + gn;
                if (mode == 1){
                    v0 += res[ci]; v1 += res[ci+1];
                    *(float2*)(C + ci) = make_float2(v0, v1);
                } else if (mode == 3){
                    v0 = v0 / (1.f + expf(-v0));
                    v1 = v1 / (1.f + expf(-v1));
                    *(__half2*)(Cp16 + ci) = __floats2half2_rn(v0, v1);
                } else if (mode == 4){
                    int slot = rowOff + gm;
                    int t = omap[slot];
                    float w = wsl[slot];
                    long long co = (long long)t*ldc + gn;
                    atomicAdd(&C[co],   w*v0);
                    atomicAdd(&C[co+1], w*v1);
                } else {
                    *(float2*)(C + ci) = make_float2(v0, v1);
                }
            }
        }
    }
}

// ======= fused flash attention: 64-row Q tiles, 128 threads, 2-stage KV, 2 CTA/SM =======
#define FSTR 72
#define QBYTES (64*FSTR*2)          // 9216
#define KVHALF (128*FSTR*2)         // 18432
#define KVSTG  (2*KVHALF)           // 36864
#define FLASH_SMEM (QBYTES + 2*KVSTG)

__global__ void __launch_bounds__(128,2) flash_attn(
    const __half* __restrict__ qh, const __half* __restrict__ kh,
    const __half* __restrict__ vh, const float* __restrict__ mask,
    __half* __restrict__ oh)
{
    extern __shared__ __align__(16) char fsm[];
    __half* sQ = (__half*)fsm;
    uint32_t uQ = smem_u32(fsm);
    uint32_t ukv0 = uQ + QBYTES;

    int tid = threadIdx.x, wid = tid >> 5, lane = tid & 31;
    int bh_ = blockIdx.y, b = bh_ >> 4, h = bh_ & 15;
    int q0 = blockIdx.x * 64;
    long long tb = (long long)b * LL;

    // KV load: 128 threads, each owns one K row + one V row (8 x 16B each)
#define FLASH_ISSUE(jt) do { \
    int st_ = (jt) & 1; \
    long long g_ = (tb + (jt)*128 + tid)*DIMM + h*HD; \
    uint32_t dk_ = ukv0 + st_*KVSTG + (uint32_t)(tid*144); \
    const __half* ks_ = kh + g_; const __half* vs_ = vh + g_; \
    _Pragma("unroll") \
    for (int i_ = 0; i_ < 8; i_++) CPASYNC(dk_ + i_*16, ks_ + i_*8, 16); \
    uint32_t dv_ = dk_ + KVHALF; \
    _Pragma("unroll") \
    for (int i_ = 0; i_ < 8; i_++) CPASYNC(dv_ + i_*16, vs_ + i_*8, 16); \
    CPCOMMIT(); } while(0)

    { // Q tile: 64 rows, each thread loads half a row (32 halves)
        int qr = tid >> 1, qhf = (tid & 1) * 32;
        long long g = (tb + q0 + qr)*DIMM + h*HD + qhf;
        uint4* d0 = (uint4*)&sQ[qr*FSTR + qhf];
        const uint4* s0 = (const uint4*)(qh + g);
        #pragma unroll
        for (int i = 0; i < 4; i++) d0[i] = s0[i];
    }
    FLASH_ISSUE(0);
    __syncthreads();

    int lr = lane & 15, ls = (lane >> 4) * 8;
    uint32_t aq[4][4];
    #pragma unroll
    for (int kc = 0; kc < 4; kc++){
        uint32_t ad = uQ + 2u*((wid*16 + lr)*FSTR + kc*16 + ls);
        LDMX4(aq[kc][0],aq[kc][1],aq[kc][2],aq[kc][3], ad);
    }

    float oacc[8][4];
    #pragma unroll
    for (int i=0;i<8;i++) for (int j=0;j<4;j++) oacc[i][j]=0.f;
    float m0r = -1e30f, m1r = -1e30f, l0r = 0.f, l1r = 0.f;

    const float* mp0 = mask + (long long)(q0 + wid*16 + (lane>>2))*LL;
    const float* mp1 = mp0 + 8*LL;
    const float SC  = 0.125f * 1.44269504f;
    const float L2E = 1.44269504f;

    for (int jt = 0; jt < 8; jt++){
        CPWAIT(0);
        __syncthreads();
        if (jt + 1 < 8) FLASH_ISSUE(jt + 1);
        uint32_t uK = ukv0 + (jt & 1)*KVSTG, uV = uK + KVHALF;

        float s[16][4];
        #pragma unroll
        for (int i=0;i<16;i++) for (int j=0;j<4;j++) s[i][j]=0.f;

        #pragma unroll
        for (int kc = 0; kc < 4; kc++){
            #pragma unroll
            for (int np = 0; np < 8; np++){
                uint32_t bk[4];
                uint32_t ad = uK + 2u*((np*16 + lr)*FSTR + kc*16 + ls);
                LDMX4(bk[0],bk[1],bk[2],bk[3], ad);
                float* c0 = s[2*np]; float* c1 = s[2*np+1];
                MMAH(c0[0],c0[1],c0[2],c0[3], aq[kc][0],aq[kc][1],aq[kc][2],aq[kc][3], bk[0],bk[2]);
                MMAH(c1[0],c1[1],c1[2],c1[3], aq[kc][0],aq[kc][1],aq[kc][2],aq[kc][3], bk[1],bk[3]);
            }
        }

        float mx0 = -1e30f, mx1 = -1e30f;
        #pragma unroll
        for (int nt = 0; nt < 16; nt++){
            int colb = jt*128 + nt*8 + (lane&3)*2;
            float2 mm0 = *(const float2*)(mp0 + colb);
            float2 mm1 = *(const float2*)(mp1 + colb);
            s[nt][0] = fmaf(s[nt][0], SC, mm0.x*L2E);
            s[nt][1] = fmaf(s[nt][1], SC, mm0.y*L2E);
            s[nt][2] = fmaf(s[nt][2], SC, mm1.x*L2E);
            s[nt][3] = fmaf(s[nt][3], SC, mm1.y*L2E);
            mx0 = fmaxf(mx0, fmaxf(s[nt][0], s[nt][1]));
            mx1 = fmaxf(mx1, fmaxf(s[nt][2], s[nt][3]));
        }
        mx0 = fmaxf(mx0, __shfl_xor_sync(0xffffffffu, mx0, 1));
        mx0 = fmaxf(mx0, __shfl_xor_sync(0xffffffffu, mx0, 2));
        mx1 = fmaxf(mx1, __shfl_xor_sync(0xffffffffu, mx1, 1));
        mx1 = fmaxf(mx1, __shfl_xor_sync(0xffffffffu, mx1, 2));

        float nm0 = fmaxf(m0r, mx0), nm1 = fmaxf(m1r, mx1);
        float al0 = exp2f(m0r - nm0), al1 = exp2f(m1r - nm1);
        m0r = nm0; m1r = nm1;

        float rs0 = 0.f, rs1 = 0.f;
        #pragma unroll
        for (int nt = 0; nt < 16; nt++){
            s[nt][0] = exp2f(s[nt][0] - nm0);
            s[nt][1] = exp2f(s[nt][1] - nm0);
            s[nt][2] = exp2f(s[nt][2] - nm1);
            s[nt][3] = exp2f(s[nt][3] - nm1);
            rs0 += s[nt][0] + s[nt][1];
            rs1 += s[nt][2] + s[nt][3];
        }
        rs0 += __shfl_xor_sync(0xffffffffu, rs0, 1);
        rs0 += __shfl_xor_sync(0xffffffffu, rs0, 2);
        rs1 += __shfl_xor_sync(0xffffffffu, rs1, 1);
        rs1 += __shfl_xor_sync(0xffffffffu, rs1, 2);
        l0r = l0r*al0 + rs0;
        l1r = l1r*al1 + rs1;
        #pragma unroll
        for (int dt = 0; dt < 8; dt++){
            oacc[dt][0] *= al0; oacc[dt][1] *= al0;
            oacc[dt][2] *= al1; oacc[dt][3] *= al1;
        }

        #pragma unroll
        for (int kc2 = 0; kc2 < 8; kc2++){
            uint32_t pa[4];
            {
                __half2 h0 = __floats2half2_rn(s[2*kc2][0],   s[2*kc2][1]);
                __half2 h1 = __floats2half2_rn(s[2*kc2][2],   s[2*kc2][3]);
                __half2 h2 = __floats2half2_rn(s[2*kc2+1][0], s[2*kc2+1][1]);
                __half2 h3 = __floats2half2_rn(s[2*kc2+1][2], s[2*kc2+1][3]);
                pa[0]=*(uint32_t*)&h0; pa[1]=*(uint32_t*)&h1; pa[2]=*(uint32_t*)&h2; pa[3]=*(uint32_t*)&h3;
            }
            #pragma unroll
            for (int dt = 0; dt < 4; dt++){
                uint32_t bv[4];
                uint32_t ad = uV + 2u*((kc2*16 + lr)*FSTR + dt*16 + ls);
                LDMX4T(bv[0],bv[1],bv[2],bv[3], ad);
                float* o0 = oacc[2*dt]; float* o1 = oacc[2*dt+1];
                MMAH(o0[0],o0[1],o0[2],o0[3], pa[0],pa[1],pa[2],pa[3], bv[0],bv[1]);
                MMAH(o1[0],o1[1],o1[2],o1[3], pa[0],pa[1],pa[2],pa[3], bv[2],bv[3]);
            }
        }
    }

    float i0 = 1.f / l0r, i1 = 1.f / l1r;
    long long r0 = tb + q0 + wid*16 + (lane>>2);
    #pragma unroll
    for (int dt = 0; dt < 8; dt++){
        long long g0 = r0*DIMM + h*HD + dt*8 + (lane&3)*2;
        long long g1 = g0 + 8*DIMM;
        *(__half2*)(oh + g0) = __floats2half2_rn(oacc[dt][0]*i0, oacc[dt][1]*i0);
        *(__half2*)(oh + g1) = __floats2half2_rn(oacc[dt][2]*i1, oacc[dt][3]*i1);
    }
}

// ---------------- misc kernels ----------------
__device__ __forceinline__ float warpReduceSum(float v){
    #pragma unroll
    for (int o=16;o;o>>=1) v += __shfl_xor_sync(0xffffffffu, v, o);
    return v;
}
__device__ float blockReduceSum(float v){
    __shared__ float sh[33];
    int lane = threadIdx.x & 31, wid = threadIdx.x >> 5;
    __syncthreads();
    v = warpReduceSum(v);
    if (lane==0) sh[wid] = v;
    __syncthreads();
    int nw = blockDim.x >> 5;
    float r = (threadIdx.x < nw) ? sh[threadIdx.x] : 0.f;
    if (wid==0){ r = warpReduceSum(r); if (lane==0) sh[32] = r; }
    __syncthreads();
    return sh[32];
}

// all weights -> fp16 in one pass; s1/s2 interleaved in 128-row blocks (mode-5 layout)
__global__ void convAll(const float* __restrict__ wq, const float* __restrict__ wk,
                        const float* __restrict__ wv, const float* __restrict__ wo,
                        const float* __restrict__ s1, const float* __restrict__ s2,
                        const float* __restrict__ s3, const float* __restrict__ fc1,
                        const float* __restrict__ fc2, __half* __restrict__ o){
    long long i = ((long long)blockIdx.x*256 + threadIdx.x)*8;
    if (i >= 26*WSEG) return;
    const float* src; long long off; long long dst = i;
    if      (i <  1*WSEG){ src = wq;  off = i; }
    else if (i <  2*WSEG){ src = wk;  off = i -  1*WSEG; }
    else if (i <  3*WSEG){ src = wv;  off = i -  2*WSEG; }
    else if (i <  4*WSEG){ src = wo;  off = i -  3*WSEG; }
    else if (i <  8*WSEG){
        long long o12 = i - 4*WSEG;
        int is2 = (o12 >= 2*WSEG);
        long long o2 = is2 ? o12 - 2*WSEG : o12;
        src = is2 ? s2 : s1; off = o2;
        int r = (int)(o2 >> 10), c = (int)(o2 & 1023);
        int j = r >> 7, rl = r & 127;
        dst = 4*WSEG + (((long long)(j*256 + is2*128 + rl)) << 10) + c;
    }
    else if (i < 10*WSEG){ src = s3;  off = i -  8*WSEG; }
    else if (i < 18*WSEG){ src = fc1; off = i - 10*WSEG; }
    else                 { src = fc2; off = i - 18*WSEG; }
    float4 a = *(const float4*)(src + off);
    float4 b = *(const float4*)(src + off + 4);
    __half2 h0 = __floats2half2_rn(a.x, a.y);
    __half2 h1 = __floats2half2_rn(a.z, a.w);
    __half2 h2 = __floats2half2_rn(b.x, b.y);
    __half2 h3 = __floats2half2_rn(b.z, b.w);
    uint4 pk;
    pk.x = *(uint32_t*)&h0; pk.y = *(uint32_t*)&h1;
    pk.z = *(uint32_t*)&h2; pk.w = *(uint32_t*)&h3;
    *(uint4*)(o + dst) = pk;
}

__global__ void __launch_bounds__(256) rmsnorm16(const float* __restrict__ x,
        const float* __restrict__ w, float* __restrict__ outf,
        __half* __restrict__ o16){
    long long row = blockIdx.x;
    float4 xv = ((const float4*)(x + row*DIMM))[threadIdx.x];
    float ss = xv.x*xv.x + xv.y*xv.y + xv.z*xv.z + xv.w*xv.w;
    float tot = blockReduceSum(ss);
    float scale = rsqrtf(tot * (1.0f/DIMM) + 1e-5f);
    float4 wv = ((const float4*)w)[threadIdx.x];
    float4 o;
    o.x = xv.x*scale*wv.x; o.y = xv.y*scale*wv.y;
    o.z = xv.z*scale*wv.z; o.w = xv.w*scale*wv.w;
    long long i = row*DIMM + threadIdx.x*4;
    if (outf) *(float4*)(outf + i) = o;
    __half2 h01 = __floats2half2_rn(o.x, o.y);
    __half2 h23 = __floats2half2_rn(o.z, o.w);
    *(uint2*)(o16 + i) = make_uint2(*(uint32_t*)&h01, *(uint32_t*)&h23);
}

__global__ void ropeConv(const float* __restrict__ qkv,
                         __half* __restrict__ q16, __half* __restrict__ k16,
                         __half* __restrict__ v16){
    int idx = blockIdx.x*blockDim.x + threadIdx.x;
    if (idx >= NTOK*NHEADS*(HD/2)) return;
    int j = idx & 31;
    int h = (idx >> 5) & 15;
    int t = idx >> 9;
    int l = t & (LL-1);
    long long bsrc = (long long)t*3072 + h*HD;
    long long bdst = (long long)t*DIMM + h*HD;
    float inv = powf(10000.f, -(float)j * (1.f/32.f));
    float ang = (float)l * inv;
    float sn, cs; sincosf(ang, &sn, &cs);
    float a = qkv[bsrc+j], b = qkv[bsrc+32+j];
    q16[bdst+j]    = __float2half_rn(a*cs - b*sn);
    q16[bdst+32+j] = __float2half_rn(a*sn + b*cs);
    a = qkv[bsrc+1024+j]; b = qkv[bsrc+1024+32+j];
    k16[bdst+j]    = __float2half_rn(a*cs - b*sn);
    k16[bdst+32+j] = __float2half_rn(a*sn + b*cs);
    v16[bdst+j]    = __float2half_rn(qkv[bsrc+2048+j]);
    v16[bdst+32+j] = __float2half_rn(qkv[bsrc+2048+32+j]);
}

__global__ void __launch_bounds__(256) gate_topk(const float* __restrict__ xf,
                                                 const float* __restrict__ gw,
                                                 int* __restrict__ topi, float* __restrict__ topw,
                                                 int* __restrict__ counts){
    int t = blockIdx.x;
    int tid = threadIdx.x;
    float4 xv = ((const float4*)(xf + (long long)t*DIMM))[tid];
    float acc[16];
    #pragma unroll
    for (int e = 0; e < 16; e++){
        float4 g = ((const float4*)(gw + (long long)e*DIMM))[tid];
        acc[e] = xv.x*g.x + xv.y*g.y + xv.z*g.z + xv.w*g.w;
    }
    #pragma unroll
    for (int e = 0; e < 16; e++) acc[e] = warpReduceSum(acc[e]);
    __shared__ float wr[8][16];
    __shared__ float lg[16];
    int lane = tid & 31, wid = tid >> 5;
    if (lane == 0){
        #pragma unroll
        for (int e = 0; e < 16; e++) wr[wid][e] = acc[e];
    }
    __syncthreads();
    if (tid < 16){
        float s = 0.f;
        #pragma unroll
        for (int w = 0; w < 8; w++) s += wr[w][tid];
        lg[tid] = s;
    }
    __syncthreads();
    if (tid == 0){
        float l0 = -3.0e38f; int i0 = 0;
        for (int e = 0; e < 16; e++) if (lg[e] > l0){ l0 = lg[e]; i0 = e; }
        float l1 = -3.0e38f; int i1 = 0;
        for (int e = 0; e < 16; e++) if (e != i0 && lg[e] > l1){ l1 = lg[e]; i1 = e; }
        float w1 = expf(l1 - l0);
        float sden = 1.f + w1;
        topi[2*t] = i0; topi[2*t+1] = i1;
        topw[2*t] = 1.f / sden; topw[2*t+1] = w1 / sden;
        atomicAdd(&counts[i0], 1);
        atomicAdd(&counts[i1], 1);
    }
}

__global__ void zero_counts(int* counts){
    if (threadIdx.x < NE) counts[threadIdx.x] = 0;
}
__global__ void scan_kernel(const int* __restrict__ counts, int* __restrict__ offs,
                            int* __restrict__ cursor){
    if (threadIdx.x == 0){
        int s = 0;
        for (int e = 0; e < NE; e++){ offs[e] = s; s += counts[e]; cursor[e] = 0; }
    }
}
__global__ void scatter_kernel(const int* __restrict__ topi, int* __restrict__ cursor,
                               const int* __restrict__ offs, const float* __restrict__ topw,
                               int* __restrict__ order, float* __restrict__ wslot){
    int t = blockIdx.x*blockDim.x + threadIdx.x;
    if (t >= NTOK) return;
    #pragma unroll
    for (int k2 = 0; k2 < 2; k2++){
        int e = topi[2*t+k2];
        int pos = atomicAdd(&cursor[e], 1);
        int slot = offs[e] + pos;
        order[slot] = t;
        wslot[slot] = topw[2*t+k2];
    }
}

// ---------------- host launcher ----------------
extern "C" void kernel_launch(void* const* d_in, const int* in_sizes, int n_in,
                              void* d_out, int out_size){
    const float* x    = (const float*)d_in[0];
    const float* mask = (const float*)d_in[1];
    const float* wq   = (const float*)d_in[2];
    const float* wk   = (const float*)d_in[3];
    const float* wv   = (const float*)d_in[4];
    const float* wo   = (const float*)d_in[5];
    const float* n1   = (const float*)d_in[6];
    const float* n2   = (const float*)d_in[7];
    const float* gw   = (const float*)d_in[8];
    const float* fc1  = (const float*)d_in[9];
    const float* fc2  = (const float*)d_in[10];
    const float* s1   = (const float*)d_in[11];
    const float* s2   = (const float*)d_in[12];
    const float* s3   = (const float*)d_in[13];
    float* out = (float*)d_out;

    void *p;
    cudaGetSymbolAddress(&p, g_qkv);    float* qkv    = (float*)p;
    cudaGetSymbolAddress(&p, g_h);      float* hbuf   = (float*)p;
    cudaGetSymbolAddress(&p, g_xf);     float* xf     = (float*)p;
    cudaGetSymbolAddress(&p, g_wh);     __half* wh   = (__half*)p;
    cudaGetSymbolAddress(&p, g_hn16);   __half* hn16 = (__half*)p;
    cudaGetSymbolAddress(&p, g_q16);    __half* q16  = (__half*)p;
    cudaGetSymbolAddress(&p, g_k16);    __half* k16  = (__half*)p;
    cudaGetSymbolAddress(&p, g_v16);    __half* v16  = (__half*)p;
    cudaGetSymbolAddress(&p, g_a16);    __half* a16  = (__half*)p;
    cudaGetSymbolAddress(&p, g_x16);    __half* x16  = (__half*)p;
    cudaGetSymbolAddress(&p, g_ta16);   __half* ta16 = (__half*)p;
    cudaGetSymbolAddress(&p, g_e16);    __half* e16  = (__half*)p;
    cudaGetSymbolAddress(&p, g_topi);   int*   topi   = (int*)p;
    cudaGetSymbolAddress(&p, g_topw);   float* topw   = (float*)p;
    cudaGetSymbolAddress(&p, g_counts); int*   counts = (int*)p;
    cudaGetSymbolAddress(&p, g_cursor); int*   cursor = (int*)p;
    cudaGetSymbolAddress(&p, g_offs);   int*   offs   = (int*)p;
    cudaGetSymbolAddress(&p, g_order);  int*   order  = (int*)p;
    cudaGetSymbolAddress(&p, g_wslot);  float* wslot  = (float*)p;

    cudaFuncSetAttribute(mm16, cudaFuncAttributeMaxDynamicSharedMemorySize, MM16_SMEM);
    cudaFuncSetAttribute(flash_attn, cudaFuncAttributeMaxDynamicSharedMemorySize, FLASH_SMEM);

    __half* W_QKV = wh;
    __half* W_O   = wh +  3*WSEG;
    __half* W_S12 = wh +  4*WSEG;
    __half* W_S3  = wh +  8*WSEG;
    __half* W_FC1 = wh + 10*WSEG;
    __half* W_FC2 = wh + 18*WSEG;

    cudaStream_t sB;
    cudaStreamCreateWithFlags(&sB, cudaStreamNonBlocking);
    cudaEvent_t eFork, eW, eX, eF1;
    cudaEventCreateWithFlags(&eFork, cudaEventDisableTiming);
    cudaEventCreateWithFlags(&eW,    cudaEventDisableTiming);
    cudaEventCreateWithFlags(&eX,    cudaEventDisableTiming);
    cudaEventCreateWithFlags(&eF1,   cudaEventDisableTiming);

    // fork: convAll on sB, rmsnorm1 on main
    cudaEventRecord(eFork, 0);
    cudaStreamWaitEvent(sB, eFork, 0);
    convAll<<<(int)(26*WSEG/2048), 256, 0, sB>>>(wq, wk, wv, wo, s1, s2, s3, fc1, fc2, wh);
    cudaEventRecord(eW, sB);
    rmsnorm16<<<NTOK, 256>>>(x, n1, nullptr, hn16);
    cudaStreamWaitEvent(0, eW, 0);       // weights ready for all GEMMs on main stream

    // QKV
    mm16<<<dim3(12,32,1),256,MM16_SMEM>>>(hn16, W_QKV, qkv, nullptr, nullptr,
        NTOK, 3*DIMM, DIMM, DIMM, DIMM, 3*DIMM, 0, nullptr, nullptr, nullptr, nullptr, nullptr, 0);
    ropeConv<<<(NTOK*NHEADS*32)/256, 256>>>(qkv, q16, k16, v16);
    flash_attn<<<dim3(16,64),128,FLASH_SMEM>>>(q16, k16, v16, mask, a16);
    mm16<<<dim3(4,32,1),256,MM16_SMEM>>>(a16, W_O, hbuf, x, nullptr,
        NTOK, DIMM, DIMM, DIMM, DIMM, DIMM, 1, nullptr, nullptr, nullptr, nullptr, nullptr, 0);
    rmsnorm16<<<NTOK, 256>>>(hbuf, n2, xf, x16);
    cudaEventRecord(eX, 0);

    // branch B: routing + expert fc1
    cudaStreamWaitEvent(sB, eX, 0);
    zero_counts<<<1,32,0,sB>>>(counts);
    gate_topk<<<NTOK,256,0,sB>>>(xf, gw, topi, topw, counts);
    scan_kernel<<<1,1,0,sB>>>(counts, offs, cursor);
    scatter_kernel<<<NTOK/256,256,0,sB>>>(topi, cursor, offs, topw, order, wslot);
    mm16<<<dim3(2,64,NE),256,MM16_SMEM,sB>>>(x16, W_FC1, nullptr, nullptr, e16,
        0, HID, DIMM, DIMM, DIMM, HID, 3, counts, offs, order, nullptr, nullptr, (long long)HID*DIMM);
    cudaEventRecord(eF1, sB);

    // main: shared expert with fused silu, then residual GEMM into out
    mm16<<<dim3(16,32,1),256,MM16_SMEM>>>(x16, W_S12, nullptr, nullptr, ta16,
        NTOK, 2*NSHARED, DIMM, DIMM, DIMM, NSHARED, 5, nullptr, nullptr, nullptr, nullptr, nullptr, 0);
    mm16<<<dim3(4,32,1),256,MM16_SMEM>>>(ta16, W_S3, out, hbuf, nullptr,
        NTOK, DIMM, NSHARED, NSHARED, NSHARED, DIMM, 1, nullptr, nullptr, nullptr, nullptr, nullptr, 0);

    // join: expert fc2 atomically combines into out
    cudaStreamWaitEvent(0, eF1, 0);
    mm16<<<dim3(4,64,NE),256,MM16_SMEM>>>(e16, W_FC2, out, nullptr, nullptr,
        0, DIMM, HID, HID, HID, DIMM, 4, counts, offs, nullptr, order, wslot, (long long)DIMM*HID);
}

// round 15
// speedup vs baseline: 1.0378x; 1.0378x over previous
#include <cuda_runtime.h>
#include <cuda_fp16.h>
#include <math.h>
#include <stdint.h>

#define BB 4
#define LL 1024
#define DIMM 1024
#define NHEADS 16
#define HD 64
#define NTOK (BB*LL)
#define HID 512
#define NE 16
#define NSHARED 2048
#define NSLOTS (NTOK*2)

// ---------------- scratch ----------------
__device__ float g_qkv[NTOK*3*DIMM];
__device__ float g_h[NTOK*DIMM];
__device__ float g_xf[NTOK*DIMM];
// fp16 buffers
#define WSEG 1048576ll
__device__ __half g_wh[26*WSEG];
__device__ __half g_hn16[NTOK*DIMM];
__device__ __half g_q16[NTOK*DIMM];
__device__ __half g_k16[NTOK*DIMM];
__device__ __half g_v16[NTOK*DIMM];
__device__ __half g_a16[NTOK*DIMM];
__device__ __half g_x16[NTOK*DIMM];
__device__ __half g_ta16[NTOK*NSHARED];
__device__ __half g_e16[NSLOTS*HID];
// routing
__device__ int   g_topi[NSLOTS];
__device__ float g_topw[NSLOTS];
__device__ int   g_counts[NE];
__device__ int   g_cursor[NE];
__device__ int   g_offs[NE];
__device__ int   g_order[NSLOTS];
__device__ float g_wslot[NSLOTS];

__device__ __forceinline__ uint32_t smem_u32(const void* p){
    uint32_t a;
    asm("{ .reg .u64 t; cvta.to.shared.u64 t, %1; cvt.u32.u64 %0, t; }" : "=r"(a) : "l"(p));
    return a;
}

#define LDMX4(r0,r1,r2,r3,addr) \
    asm volatile("ldmatrix.sync.aligned.m8n8.x4.shared.b16 {%0,%1,%2,%3}, [%4];" \
        : "=r"(r0),"=r"(r1),"=r"(r2),"=r"(r3) : "r"(addr))
#define LDMX4T(r0,r1,r2,r3,addr) \
    asm volatile("ldmatrix.sync.aligned.m8n8.x4.trans.shared.b16 {%0,%1,%2,%3}, [%4];" \
        : "=r"(r0),"=r"(r1),"=r"(r2),"=r"(r3) : "r"(addr))

#define MMAH(c0,c1,c2,c3,a0,a1,a2,a3,b0,b1) \
    asm volatile("mma.sync.aligned.m16n8k16.row.col.f32.f16.f16.f32 " \
        "{%0,%1,%2,%3}, {%4,%5,%6,%7}, {%8,%9}, {%0,%1,%2,%3};" \
        : "+f"(c0),"+f"(c1),"+f"(c2),"+f"(c3) \
        : "r"(a0),"r"(a1),"r"(a2),"r"(a3), "r"(b0),"r"(b1))

#define CPASYNC(dst,src,sz) \
    asm volatile("cp.async.cg.shared.global [%0], [%1], 16, %2;" :: "r"(dst), "l"(src), "r"(sz))
#define CPCOMMIT() asm volatile("cp.async.commit_group;")
#define CPWAIT(n)  asm volatile("cp.async.wait_group %0;" :: "n"(n))

// ========== fp16 GEMM: C = A * B^T ; 128x256 tile, 64x64 warp tile, K-chunk 128 ==========
// mode: 0 fp32 out, 1 fp32 += res, 3 silu->fp16, 4 atomic MoE combine,
//       5 paired silu: cols 0-127 = a1, 128-255 = a2; out fp16 silu(a1)*a2
#define ROWB 272                    // bytes per smem row (128 halves + 8 pad)
#define STAGE_BYTES (384*ROWB)      // A 128 rows + B 256 rows = 104448 B
#define NSTAGE 2
#define MM16_SMEM (NSTAGE*STAGE_BYTES)   // 208896 B

__global__ void __launch_bounds__(256,1) mm16(
    const __half* __restrict__ Ah, const __half* __restrict__ Bh,
    float* __restrict__ C, const float* __restrict__ res,
    __half* __restrict__ Cp16,
    int M, int N, int K, int lda, int ldb, int ldc, int mode,
    const int* __restrict__ counts, const int* __restrict__ offs,
    const int* __restrict__ rows,
    const int* __restrict__ omap, const float* __restrict__ wsl,
    long long bStrideE)
{
    extern __shared__ __align__(16) char dsm[];
    __shared__ int rsrc[128];
    uint32_t ub = smem_u32(dsm);
    int tid = threadIdx.x, wid = tid >> 5, lane = tid & 31;
    int e = blockIdx.z;

    int Mloc = M, rowOff = 0;
    const __half* Bp = Bh;
    if (counts){ Mloc = counts[e]; rowOff = offs[e]; Bp = Bh + (long long)e*bStrideE; }
    int m0 = blockIdx.y * 128;
    if (m0 >= Mloc) return;
    int n0 = blockIdx.x * 256;

    for (int i = tid; i < 128; i += 256){
        int gr = m0 + i;
        rsrc[i] = (gr < Mloc) ? (rows ? rows[rowOff + gr] : (counts ? rowOff + gr : gr)) : -1;
    }
    __syncthreads();

    // copy plan: each thread owns parts {p, p+8} (16B each) of
    // 4 gathered A-rows (r0+32i) and 8 strided B-rows (r0+32i).
    int r0 = tid >> 3, part = tid & 7;
    uint32_t dbase = (uint32_t)(r0*ROWB + part*16);
    const __half* ap[4]; int asz[4];
    #pragma unroll
    for (int i = 0; i < 4; i++){
        int s = rsrc[r0 + 32*i];
        asz[i] = (s >= 0) ? 16 : 0;
        ap[i] = Ah + (long long)((s >= 0) ? s : 0)*lda + part*8;
    }
    const __half* bb = Bp + (long long)(n0 + r0)*ldb + part*8;
    long long str32 = 32ll*ldb;

#define MM16_ISSUE(stg, kc) do { \
    uint32_t dd = ub + (stg)*STAGE_BYTES + dbase; int ko = (kc)*128; \
    _Pragma("unroll") \
    for (int i = 0; i < 4; i++){ \
        CPASYNC(dd + 32*i*ROWB,       ap[i]+ko,    asz[i]); \
        CPASYNC(dd + 32*i*ROWB + 128, ap[i]+ko+64, asz[i]); \
    } \
    _Pragma("unroll") \
    for (int i = 0; i < 8; i++){ \
        CPASYNC(dd+(128+32*i)*ROWB,       bb + i*str32 + ko,    16); \
        CPASYNC(dd+(128+32*i)*ROWB + 128, bb + i*str32 + ko+64, 16); \
    } \
    CPCOMMIT(); } while(0)

    float acc[4][8][4];
    #pragma unroll
    for (int i=0;i<4;i++) for (int j=0;j<8;j++) for (int f=0;f<4;f++) acc[i][j][f]=0.f;

    int wm = (wid >> 2) * 64, wn = (wid & 3) * 64;
    int lrow = lane & 15, lsel = (lane >> 4) * 8;
    int nk = K >> 7;

    MM16_ISSUE(0, 0);
    for (int kc = 0; kc < nk; kc++){
        CPWAIT(0);
        __syncthreads();
        if (kc + 1 < nk) MM16_ISSUE((kc+1)&1, kc+1);
        uint32_t us = ub + (kc & 1)*STAGE_BYTES;
        #pragma unroll
        for (int ks = 0; ks < 8; ks++){
            int kofs2 = (ks*16 + lsel)*2;
            uint32_t ah[4][4], bh[4][4];
            #pragma unroll
            for (int mt = 0; mt < 4; mt++){
                uint32_t ad = us + (uint32_t)((wm + mt*16 + lrow)*ROWB) + kofs2;
                LDMX4(ah[mt][0],ah[mt][1],ah[mt][2],ah[mt][3], ad);
            }
            #pragma unroll
            for (int j = 0; j < 4; j++){
                uint32_t bd = us + (uint32_t)((128 + wn + j*16 + lrow)*ROWB) + kofs2;
                LDMX4(bh[j][0],bh[j][1],bh[j][2],bh[j][3], bd);
            }
            #pragma unroll
            for (int mt = 0; mt < 4; mt++){
                #pragma unroll
                for (int j = 0; j < 4; j++){
                    float* c0 = acc[mt][2*j];
                    float* c1 = acc[mt][2*j+1];
                    MMAH(c0[0],c0[1],c0[2],c0[3], ah[mt][0],ah[mt][1],ah[mt][2],ah[mt][3], bh[j][0],bh[j][2]);
                    MMAH(c1[0],c1[1],c1[2],c1[3], ah[mt][0],ah[mt][1],ah[mt][2],ah[mt][3], bh[j][1],bh[j][3]);
                }
            }
        }
    }

    int rbase = lane >> 2, cbase = (lane & 3) * 2;

    if (mode == 5){
        // paired silu epilogue: a1 = cols 0..127, a2 = cols 128..255 (same out cols)
        float* stage = (float*)dsm;    // 128 x 132 fp32
        __syncthreads();               // pipeline smem dead, reuse
        if ((wid & 3) >= 2){
            int cb = wn - 128;
            #pragma unroll
            for (int mt = 0; mt < 4; mt++)
                #pragma unroll
                for (int nt = 0; nt < 8; nt++)
                    #pragma unroll
                    for (int half = 0; half < 2; half++){
                        int lm = wm + mt*16 + rbase + half*8;
                        int c = cb + nt*8 + cbase;
                        stage[lm*132 + c]   = acc[mt][nt][2*half];
                        stage[lm*132 + c+1] = acc[mt][nt][2*half+1];
                    }
        }
        __syncthreads();
        if ((wid & 3) < 2){
            int n0h = blockIdx.x * 128;
            #pragma unroll
            for (int mt = 0; mt < 4; mt++)
                #pragma unroll
                for (int nt = 0; nt < 8; nt++)
                    #pragma unroll
                    for (int half = 0; half < 2; half++){
                        int lm = wm + mt*16 + rbase + half*8;
                        int c = wn + nt*8 + cbase;
                        float a1x = acc[mt][nt][2*half];
                        float a1y = acc[mt][nt][2*half+1];
                        float a2x = stage[lm*132 + c];
                        float a2y = stage[lm*132 + c+1];
                        float ox = a1x/(1.f+expf(-a1x))*a2x;
                        float oy = a1y/(1.f+expf(-a1y))*a2y;
                        long long ci = (long long)(m0 + lm)*ldc + n0h + c;
                        *(__half2*)(Cp16 + ci) = __floats2half2_rn(ox, oy);
                    }
        }
        return;
    }

    #pragma unroll
    for (int mt = 0; mt < 4; mt++){
        #pragma unroll
        for (int nt = 0; nt < 8; nt++){
            int gn = n0 + wn + nt*8 + cbase;
            #pragma unroll
            for (int half = 0; half < 2; half++){
                int gm = m0 + wm + mt*16 + rbase + half*8;
                if (gm >= Mloc) continue;
                float v0 = acc[mt][nt][2*half];
                float v1 = acc[mt][nt][2*half+1];
                long long ci = (long long)(rowOff + gm)*ldc + gn;
                if (mode == 1){
                    v0 += res[ci]; v1 += res[ci+1];
                    *(float2*)(C + ci) = make_float2(v0, v1);
                } else if (mode == 3){
                    v0 = v0 / (1.f + expf(-v0));
                    v1 = v1 / (1.f + expf(-v1));
                    *(__half2*)(Cp16 + ci) = __floats2half2_rn(v0, v1);
                } else if (mode == 4){
                    int slot = rowOff + gm;
                    int t = omap[slot];
                    float w = wsl[slot];
                    long long co = (long long)t*ldc + gn;
                    atomicAdd(&C[co],   w*v0);
                    atomicAdd(&C[co+1], w*v1);
                } else {
                    *(float2*)(C + ci) = make_float2(v0, v1);
                }
            }
        }
    }
}

// ===================== fused flash attention, 3-stage cp.async K/V (R13 proven) =====================
#define FSTR 72
#define KVHALF (128*FSTR*2)
#define KVSTG  (2*KVHALF)
#define FLASH_SMEM (KVHALF + 3*KVSTG)

__global__ void __launch_bounds__(256,1) flash_attn(
    const __half* __restrict__ qh, const __half* __restrict__ kh,
    const __half* __restrict__ vh, const float* __restrict__ mask,
    __half* __restrict__ oh)
{
    extern __shared__ __align__(16) char fsm[];
    __half* sQ = (__half*)fsm;
    uint32_t uQ = smem_u32(fsm);
    uint32_t ukv0 = uQ + KVHALF;

    int tid = threadIdx.x, wid = tid >> 5, lane = tid & 31;
    int bh_ = blockIdx.y, b = bh_ >> 4, h = bh_ & 15;
    int q0 = blockIdx.x * 128;
    long long tb = (long long)b * LL;
    int crow = tid >> 1, chalf = (tid & 1) * 32;

#define FLASH_ISSUE(jt) do { \
    int st_ = (jt) % 3; \
    long long g_ = (tb + (jt)*128 + crow)*DIMM + h*HD + chalf; \
    uint32_t dk_ = ukv0 + st_*KVSTG + (uint32_t)(crow*144 + chalf*2); \
    const __half* ks_ = kh + g_; const __half* vs_ = vh + g_; \
    CPASYNC(dk_,    ks_,    16); CPASYNC(dk_+16, ks_+8,  16); \
    CPASYNC(dk_+32, ks_+16, 16); CPASYNC(dk_+48, ks_+24, 16); \
    uint32_t dv_ = dk_ + KVHALF; \
    CPASYNC(dv_,    vs_,    16); CPASYNC(dv_+16, vs_+8,  16); \
    CPASYNC(dv_+32, vs_+16, 16); CPASYNC(dv_+48, vs_+24, 16); \
    CPCOMMIT(); } while(0)

    {
        long long g = (tb + q0 + crow)*DIMM + h*HD + chalf;
        uint4* d0 = (uint4*)&sQ[crow*FSTR + chalf];
        const uint4* s0 = (const uint4*)(qh + g);
        #pragma unroll
        for (int i = 0; i < 4; i++) d0[i] = s0[i];
    }
    FLASH_ISSUE(0);
    FLASH_ISSUE(1);
    __syncthreads();

    int lr = lane & 15, ls = (lane >> 4) * 8;
    uint32_t aq[4][4];
    #pragma unroll
    for (int kc = 0; kc < 4; kc++){
        uint32_t ad = uQ + 2u*((wid*16 + lr)*FSTR + kc*16 + ls);
        LDMX4(aq[kc][0],aq[kc][1],aq[kc][2],aq[kc][3], ad);
    }

    float oacc[8][4];
    #pragma unroll
    for (int i=0;i<8;i++) for (int j=0;j<4;j++) oacc[i][j]=0.f;
    float m0r = -1e30f, m1r = -1e30f, l0r = 0.f, l1r = 0.f;

    const float* mp0 = mask + (long long)(q0 + wid*16 + (lane>>2))*LL;
    const float* mp1 = mp0 + 8*LL;
    const float SC  = 0.125f * 1.44269504f;
    const float L2E = 1.44269504f;

    for (int jt = 0; jt < 8; jt++){
        if (jt < 7) CPWAIT(1); else CPWAIT(0);
        __syncthreads();
        if (jt + 2 < 8) FLASH_ISSUE(jt + 2);
        uint32_t uK = ukv0 + (jt % 3)*KVSTG, uV = uK + KVHALF;

        float s[16][4];
        #pragma unroll
        for (int i=0;i<16;i++) for (int j=0;j<4;j++) s[i][j]=0.f;

        #pragma unroll
        for (int kc = 0; kc < 4; kc++){
            #pragma unroll
            for (int np = 0; np < 8; np++){
                uint32_t bk[4];
                uint32_t ad = uK + 2u*((np*16 + lr)*FSTR + kc*16 + ls);
                LDMX4(bk[0],bk[1],bk[2],bk[3], ad);
                float* c0 = s[2*np]; float* c1 = s[2*np+1];
                MMAH(c0[0],c0[1],c0[2],c0[3], aq[kc][0],aq[kc][1],aq[kc][2],aq[kc][3], bk[0],bk[2]);
                MMAH(c1[0],c1[1],c1[2],c1[3], aq[kc][0],aq[kc][1],aq[kc][2],aq[kc][3], bk[1],bk[3]);
            }
        }

        float mx0 = -1e30f, mx1 = -1e30f;
        #pragma unroll
        for (int nt = 0; nt < 16; nt++){
            int colb = jt*128 + nt*8 + (lane&3)*2;
            float2 mm0 = *(const float2*)(mp0 + colb);
            float2 mm1 = *(const float2*)(mp1 + colb);
            s[nt][0] = fmaf(s[nt][0], SC, mm0.x*L2E);
            s[nt][1] = fmaf(s[nt][1], SC, mm0.y*L2E);
            s[nt][2] = fmaf(s[nt][2], SC, mm1.x*L2E);
            s[nt][3] = fmaf(s[nt][3], SC, mm1.y*L2E);
            mx0 = fmaxf(mx0, fmaxf(s[nt][0], s[nt][1]));
            mx1 = fmaxf(mx1, fmaxf(s[nt][2], s[nt][3]));
        }
        mx0 = fmaxf(mx0, __shfl_xor_sync(0xffffffffu, mx0, 1));
        mx0 = fmaxf(mx0, __shfl_xor_sync(0xffffffffu, mx0, 2));
        mx1 = fmaxf(mx1, __shfl_xor_sync(0xffffffffu, mx1, 1));
        mx1 = fmaxf(mx1, __shfl_xor_sync(0xffffffffu, mx1, 2));

        float nm0 = fmaxf(m0r, mx0), nm1 = fmaxf(m1r, mx1);
        float al0 = exp2f(m0r - nm0), al1 = exp2f(m1r - nm1);
        m0r = nm0; m1r = nm1;

        float rs0 = 0.f, rs1 = 0.f;
        #pragma unroll
        for (int nt = 0; nt < 16; nt++){
            s[nt][0] = exp2f(s[nt][0] - nm0);
            s[nt][1] = exp2f(s[nt][1] - nm0);
            s[nt][2] = exp2f(s[nt][2] - nm1);
            s[nt][3] = exp2f(s[nt][3] - nm1);
            rs0 += s[nt][0] + s[nt][1];
            rs1 += s[nt][2] + s[nt][3];
        }
        rs0 += __shfl_xor_sync(0xffffffffu, rs0, 1);
        rs0 += __shfl_xor_sync(0xffffffffu, rs0, 2);
        rs1 += __shfl_xor_sync(0xffffffffu, rs1, 1);
        rs1 += __shfl_xor_sync(0xffffffffu, rs1, 2);
        l0r = l0r*al0 + rs0;
        l1r = l1r*al1 + rs1;
        #pragma unroll
        for (int dt = 0; dt < 8; dt++){
            oacc[dt][0] *= al0; oacc[dt][1] *= al0;
            oacc[dt][2] *= al1; oacc[dt][3] *= al1;
        }

        #pragma unroll
        for (int kc2 = 0; kc2 < 8; kc2++){
            uint32_t pa[4];
            {
                __half2 h0 = __floats2half2_rn(s[2*kc2][0],   s[2*kc2][1]);
                __half2 h1 = __floats2half2_rn(s[2*kc2][2],   s[2*kc2][3]);
                __half2 h2 = __floats2half2_rn(s[2*kc2+1][0], s[2*kc2+1][1]);
                __half2 h3 = __floats2half2_rn(s[2*kc2+1][2], s[2*kc2+1][3]);
                pa[0]=*(uint32_t*)&h0; pa[1]=*(uint32_t*)&h1; pa[2]=*(uint32_t*)&h2; pa[3]=*(uint32_t*)&h3;
            }
            #pragma unroll
            for (int dt = 0; dt < 4; dt++){
                uint32_t bv[4];
                uint32_t ad = uV + 2u*((kc2*16 + lr)*FSTR + dt*16 + ls);
                LDMX4T(bv[0],bv[1],bv[2],bv[3], ad);
                float* o0 = oacc[2*dt]; float* o1 = oacc[2*dt+1];
                MMAH(o0[0],o0[1],o0[2],o0[3], pa[0],pa[1],pa[2],pa[3], bv[0],bv[1]);
                MMAH(o1[0],o1[1],o1[2],o1[3], pa[0],pa[1],pa[2],pa[3], bv[2],bv[3]);
            }
        }
    }

    float i0 = 1.f / l0r, i1 = 1.f / l1r;
    long long r0 = tb + q0 + wid*16 + (lane>>2);
    #pragma unroll
    for (int dt = 0; dt < 8; dt++){
        long long g0 = r0*DIMM + h*HD + dt*8 + (lane&3)*2;
        long long g1 = g0 + 8*DIMM;
        *(__half2*)(oh + g0) = __floats2half2_rn(oacc[dt][0]*i0, oacc[dt][1]*i0);
        *(__half2*)(oh + g1) = __floats2half2_rn(oacc[dt][2]*i1, oacc[dt][3]*i1);
    }
}

// ---------------- misc kernels ----------------
__device__ __forceinline__ float warpReduceSum(float v){
    #pragma unroll
    for (int o=16;o;o>>=1) v += __shfl_xor_sync(0xffffffffu, v, o);
    return v;
}
__device__ float blockReduceSum(float v){
    __shared__ float sh[33];
    int lane = threadIdx.x & 31, wid = threadIdx.x >> 5;
    __syncthreads();
    v = warpReduceSum(v);
    if (lane==0) sh[wid] = v;
    __syncthreads();
    int nw = blockDim.x >> 5;
    float r = (threadIdx.x < nw) ? sh[threadIdx.x] : 0.f;
    if (wid==0){ r = warpReduceSum(r); if (lane==0) sh[32] = r; }
    __syncthreads();
    return sh[32];
}

// all weights -> fp16 in one pass; s1/s2 interleaved in 128-row blocks (mode-5 layout)
__global__ void convAll(const float* __restrict__ wq, const float* __restrict__ wk,
                        const float* __restrict__ wv, const float* __restrict__ wo,
                        const float* __restrict__ s1, const float* __restrict__ s2,
                        const float* __restrict__ s3, const float* __restrict__ fc1,
                        const float* __restrict__ fc2, __half* __restrict__ o){
    long long i = ((long long)blockIdx.x*256 + threadIdx.x)*8;
    if (i >= 26*WSEG) return;
    const float* src; long long off; long long dst = i;
    if      (i <  1*WSEG){ src = wq;  off = i; }
    else if (i <  2*WSEG){ src = wk;  off = i -  1*WSEG; }
    else if (i <  3*WSEG){ src = wv;  off = i -  2*WSEG; }
    else if (i <  4*WSEG){ src = wo;  off = i -  3*WSEG; }
    else if (i <  8*WSEG){
        long long o12 = i - 4*WSEG;
        int is2 = (o12 >= 2*WSEG);
        long long o2 = is2 ? o12 - 2*WSEG : o12;
        src = is2 ? s2 : s1; off = o2;
        int r = (int)(o2 >> 10), c = (int)(o2 & 1023);
        int j = r >> 7, rl = r & 127;
        dst = 4*WSEG + (((long long)(j*256 + is2*128 + rl)) << 10) + c;
    }
    else if (i < 10*WSEG){ src = s3;  off = i -  8*WSEG; }
    else if (i < 18*WSEG){ src = fc1; off = i - 10*WSEG; }
    else                 { src = fc2; off = i - 18*WSEG; }
    float4 a = *(const float4*)(src + off);
    float4 b = *(const float4*)(src + off + 4);
    __half2 h0 = __floats2half2_rn(a.x, a.y);
    __half2 h1 = __floats2half2_rn(a.z, a.w);
    __half2 h2 = __floats2half2_rn(b.x, b.y);
    __half2 h3 = __floats2half2_rn(b.z, b.w);
    uint4 pk;
    pk.x = *(uint32_t*)&h0; pk.y = *(uint32_t*)&h1;
    pk.z = *(uint32_t*)&h2; pk.w = *(uint32_t*)&h3;
    *(uint4*)(o + dst) = pk;
}

__global__ void __launch_bounds__(256) rmsnorm16(const float* __restrict__ x,
        const float* __restrict__ w, float* __restrict__ outf,
        __half* __restrict__ o16){
    long long row = blockIdx.x;
    float4 xv = ((const float4*)(x + row*DIMM))[threadIdx.x];
    float ss = xv.x*xv.x + xv.y*xv.y + xv.z*xv.z + xv.w*xv.w;
    float tot = blockReduceSum(ss);
    float scale = rsqrtf(tot * (1.0f/DIMM) + 1e-5f);
    float4 wv = ((const float4*)w)[threadIdx.x];
    float4 o;
    o.x = xv.x*scale*wv.x; o.y = xv.y*scale*wv.y;
    o.z = xv.z*scale*wv.z; o.w = xv.w*scale*wv.w;
    long long i = row*DIMM + threadIdx.x*4;
    if (outf) *(float4*)(outf + i) = o;
    __half2 h01 = __floats2half2_rn(o.x, o.y);
    __half2 h23 = __floats2half2_rn(o.z, o.w);
    *(uint2*)(o16 + i) = make_uint2(*(uint32_t*)&h01, *(uint32_t*)&h23);
}

__global__ void ropeConv(const float* __restrict__ qkv,
                         __half* __restrict__ q16, __half* __restrict__ k16,
                         __half* __restrict__ v16){
    int idx = blockIdx.x*blockDim.x + threadIdx.x;
    if (idx >= NTOK*NHEADS*(HD/2)) return;
    int j = idx & 31;
    int h = (idx >> 5) & 15;
    int t = idx >> 9;
    int l = t & (LL-1);
    long long bsrc = (long long)t*3072 + h*HD;
    long long bdst = (long long)t*DIMM + h*HD;
    float inv = powf(10000.f, -(float)j * (1.f/32.f));
    float ang = (float)l * inv;
    float sn, cs; sincosf(ang, &sn, &cs);
    float a = qkv[bsrc+j], b = qkv[bsrc+32+j];
    q16[bdst+j]    = __float2half_rn(a*cs - b*sn);
    q16[bdst+32+j] = __float2half_rn(a*sn + b*cs);
    a = qkv[bsrc+1024+j]; b = qkv[bsrc+1024+32+j];
    k16[bdst+j]    = __float2half_rn(a*cs - b*sn);
    k16[bdst+32+j] = __float2half_rn(a*sn + b*cs);
    v16[bdst+j]    = __float2half_rn(qkv[bsrc+2048+j]);
    v16[bdst+32+j] = __float2half_rn(qkv[bsrc+2048+32+j]);
}

__global__ void __launch_bounds__(256) gate_topk(const float* __restrict__ xf,
                                                 const float* __restrict__ gw,
                                                 int* __restrict__ topi, float* __restrict__ topw,
                                                 int* __restrict__ counts){
    int t = blockIdx.x;
    int tid = threadIdx.x;
    float4 xv = ((const float4*)(xf + (long long)t*DIMM))[tid];
    float acc[16];
    #pragma unroll
    for (int e = 0; e < 16; e++){
        float4 g = ((const float4*)(gw + (long long)e*DIMM))[tid];
        acc[e] = xv.x*g.x + xv.y*g.y + xv.z*g.z + xv.w*g.w;
    }
    #pragma unroll
    for (int e = 0; e < 16; e++) acc[e] = warpReduceSum(acc[e]);
    __shared__ float wr[8][16];
    __shared__ float lg[16];
    int lane = tid & 31, wid = tid >> 5;
    if (lane == 0){
        #pragma unroll
        for (int e = 0; e < 16; e++) wr[wid][e] = acc[e];
    }
    __syncthreads();
    if (tid < 16){
        float s = 0.f;
        #pragma unroll
        for (int w = 0; w < 8; w++) s += wr[w][tid];
        lg[tid] = s;
    }
    __syncthreads();
    if (tid == 0){
        float l0 = -3.0e38f; int i0 = 0;
        for (int e = 0; e < 16; e++) if (lg[e] > l0){ l0 = lg[e]; i0 = e; }
        float l1 = -3.0e38f; int i1 = 0;
        for (int e = 0; e < 16; e++) if (e != i0 && lg[e] > l1){ l1 = lg[e]; i1 = e; }
        float w1 = expf(l1 - l0);
        float sden = 1.f + w1;
        topi[2*t] = i0; topi[2*t+1] = i1;
        topw[2*t] = 1.f / sden; topw[2*t+1] = w1 / sden;
        atomicAdd(&counts[i0], 1);
        atomicAdd(&counts[i1], 1);
    }
}

__global__ void zero_counts(int* counts){
    if (threadIdx.x < NE) counts[threadIdx.x] = 0;
}
__global__ void scan_kernel(const int* __restrict__ counts, int* __restrict__ offs,
                            int* __restrict__ cursor){
    if (threadIdx.x == 0){
        int s = 0;
        for (int e = 0; e < NE; e++){ offs[e] = s; s += counts[e]; cursor[e] = 0; }
    }
}
__global__ void scatter_kernel(const int* __restrict__ topi, int* __restrict__ cursor,
                               const int* __restrict__ offs, const float* __restrict__ topw,
                               int* __restrict__ order, float* __restrict__ wslot){
    int t = blockIdx.x*blockDim.x + threadIdx.x;
    if (t >= NTOK) return;
    #pragma unroll
    for (int k2 = 0; k2 < 2; k2++){
        int e = topi[2*t+k2];
        int pos = atomicAdd(&cursor[e], 1);
        int slot = offs[e] + pos;
        order[slot] = t;
        wslot[slot] = topw[2*t+k2];
    }
}

// ---------------- host launcher ----------------
extern "C" void kernel_launch(void* const* d_in, const int* in_sizes, int n_in,
                              void* d_out, int out_size){
    const float* x    = (const float*)d_in[0];
    const float* mask = (const float*)d_in[1];
    const float* wq   = (const float*)d_in[2];
    const float* wk   = (const float*)d_in[3];
    const float* wv   = (const float*)d_in[4];
    const float* wo   = (const float*)d_in[5];
    const float* n1   = (const float*)d_in[6];
    const float* n2   = (const float*)d_in[7];
    const float* gw   = (const float*)d_in[8];
    const float* fc1  = (const float*)d_in[9];
    const float* fc2  = (const float*)d_in[10];
    const float* s1   = (const float*)d_in[11];
    const float* s2   = (const float*)d_in[12];
    const float* s3   = (const float*)d_in[13];
    float* out = (float*)d_out;

    void *p;
    cudaGetSymbolAddress(&p, g_qkv);    float* qkv    = (float*)p;
    cudaGetSymbolAddress(&p, g_h);      float* hbuf   = (float*)p;
    cudaGetSymbolAddress(&p, g_xf);     float* xf     = (float*)p;
    cudaGetSymbolAddress(&p, g_wh);     __half* wh   = (__half*)p;
    cudaGetSymbolAddress(&p, g_hn16);   __half* hn16 = (__half*)p;
    cudaGetSymbolAddress(&p, g_q16);    __half* q16  = (__half*)p;
    cudaGetSymbolAddress(&p, g_k16);    __half* k16  = (__half*)p;
    cudaGetSymbolAddress(&p, g_v16);    __half* v16  = (__half*)p;
    cudaGetSymbolAddress(&p, g_a16);    __half* a16  = (__half*)p;
    cudaGetSymbolAddress(&p, g_x16);    __half* x16  = (__half*)p;
    cudaGetSymbolAddress(&p, g_ta16);   __half* ta16 = (__half*)p;
    cudaGetSymbolAddress(&p, g_e16);    __half* e16  = (__half*)p;
    cudaGetSymbolAddress(&p, g_topi);   int*   topi   = (int*)p;
    cudaGetSymbolAddress(&p, g_topw);   float* topw   = (float*)p;
    cudaGetSymbolAddress(&p, g_counts); int*   counts = (int*)p;
    cudaGetSymbolAddress(&p, g_cursor); int*   cursor = (int*)p;
    cudaGetSymbolAddress(&p, g_offs);   int*   offs   = (int*)p;
    cudaGetSymbolAddress(&p, g_order);  int*   order  = (int*)p;
    cudaGetSymbolAddress(&p, g_wslot);  float* wslot  = (float*)p;

    cudaFuncSetAttribute(mm16, cudaFuncAttributeMaxDynamicSharedMemorySize, MM16_SMEM);
    cudaFuncSetAttribute(flash_attn, cudaFuncAttributeMaxDynamicSharedMemorySize, FLASH_SMEM);

    __half* W_QKV = wh;
    __half* W_O   = wh +  3*WSEG;
    __half* W_S12 = wh +  4*WSEG;
    __half* W_S3  = wh +  8*WSEG;
    __half* W_FC1 = wh + 10*WSEG;
    __half* W_FC2 = wh + 18*WSEG;

    cudaStream_t sB;
    cudaStreamCreateWithFlags(&sB, cudaStreamNonBlocking);
    cudaEvent_t eFork, eW, eX, eF1;
    cudaEventCreateWithFlags(&eFork, cudaEventDisableTiming);
    cudaEventCreateWithFlags(&eW,    cudaEventDisableTiming);
    cudaEventCreateWithFlags(&eX,    cudaEventDisableTiming);
    cudaEventCreateWithFlags(&eF1,   cudaEventDisableTiming);

    // fork: convAll on sB, rmsnorm1 on main
    cudaEventRecord(eFork, 0);
    cudaStreamWaitEvent(sB, eFork, 0);
    convAll<<<(int)(26*WSEG/2048), 256, 0, sB>>>(wq, wk, wv, wo, s1, s2, s3, fc1, fc2, wh);
    cudaEventRecord(eW, sB);
    rmsnorm16<<<NTOK, 256>>>(x, n1, nullptr, hn16);
    cudaStreamWaitEvent(0, eW, 0);       // weights ready for all GEMMs on main stream

    // QKV
    mm16<<<dim3(12,32,1),256,MM16_SMEM>>>(hn16, W_QKV, qkv, nullptr, nullptr,
        NTOK, 3*DIMM, DIMM, DIMM, DIMM, 3*DIMM, 0, nullptr, nullptr, nullptr, nullptr, nullptr, 0);
    ropeConv<<<(NTOK*NHEADS*32)/256, 256>>>(qkv, q16, k16, v16);
    flash_attn<<<dim3(8,64),256,FLASH_SMEM>>>(q16, k16, v16, mask, a16);
    mm16<<<dim3(4,32,1),256,MM16_SMEM>>>(a16, W_O, hbuf, x, nullptr,
        NTOK, DIMM, DIMM, DIMM, DIMM, DIMM, 1, nullptr, nullptr, nullptr, nullptr, nullptr, 0);
    rmsnorm16<<<NTOK, 256>>>(hbuf, n2, xf, x16);
    cudaEventRecord(eX, 0);

    // branch B: routing + expert fc1
    cudaStreamWaitEvent(sB, eX, 0);
    zero_counts<<<1,32,0,sB>>>(counts);
    gate_topk<<<NTOK,256,0,sB>>>(xf, gw, topi, topw, counts);
    scan_kernel<<<1,1,0,sB>>>(counts, offs, cursor);
    scatter_kernel<<<NTOK/256,256,0,sB>>>(topi, cursor, offs, topw, order, wslot);
    mm16<<<dim3(2,64,NE),256,MM16_SMEM,sB>>>(x16, W_FC1, nullptr, nullptr, e16,
        0, HID, DIMM, DIMM, DIMM, HID, 3, counts, offs, order, nullptr, nullptr, (long long)HID*DIMM);
    cudaEventRecord(eF1, sB);

    // main: shared expert with fused silu, then residual GEMM into out
    mm16<<<dim3(16,32,1),256,MM16_SMEM>>>(x16, W_S12, nullptr, nullptr, ta16,
        NTOK, 2*NSHARED, DIMM, DIMM, DIMM, NSHARED, 5, nullptr, nullptr, nullptr, nullptr, nullptr, 0);
    mm16<<<dim3(4,32,1),256,MM16_SMEM>>>(ta16, W_S3, out, hbuf, nullptr,
        NTOK, DIMM, NSHARED, NSHARED, NSHARED, DIMM, 1, nullptr, nullptr, nullptr, nullptr, nullptr, 0);

    // join: expert fc2 atomically combines into out
    cudaStreamWaitEvent(0, eF1, 0);
    mm16<<<dim3(4,64,NE),256,MM16_SMEM>>>(e16, W_FC2, out, nullptr, nullptr,
        0, DIMM, HID, HID, HID, DIMM, 4, counts, offs, nullptr, order, wslot, (long long)DIMM*HID);
}

// round 16
// speedup vs baseline: 1.0445x; 1.0065x over previous
#include <cuda_runtime.h>
#include <cuda_fp16.h>
#include <math.h>
#include <stdint.h>

#define BB 4
#define LL 1024
#define DIMM 1024
#define NHEADS 16
#define HD 64
#define NTOK (BB*LL)
#define HID 512
#define NE 16
#define NSHARED 2048
#define NSLOTS (NTOK*2)

// ---------------- scratch ----------------
__device__ float g_qkv[NTOK*3*DIMM];
__device__ float g_h[NTOK*DIMM];
__device__ float g_xf[NTOK*DIMM];
// fp16 buffers
#define WSEG 1048576ll
__device__ __half g_wh[26*WSEG];
__device__ __half g_hn16[NTOK*DIMM];
__device__ __half g_q16[NTOK*DIMM];
__device__ __half g_k16[NTOK*DIMM];
__device__ __half g_v16[NTOK*DIMM];
__device__ __half g_a16[NTOK*DIMM];
__device__ __half g_x16[NTOK*DIMM];
__device__ __half g_ta16[NTOK*NSHARED];
__device__ __half g_e16[NSLOTS*HID];
// routing
__device__ int   g_topi[NSLOTS];
__device__ float g_topw[NSLOTS];
__device__ int   g_counts[NE];
__device__ int   g_cursor[NE];
__device__ int   g_offs[NE];
__device__ int   g_order[NSLOTS];
__device__ float g_wslot[NSLOTS];

__device__ __forceinline__ uint32_t smem_u32(const void* p){
    uint32_t a;
    asm("{ .reg .u64 t; cvta.to.shared.u64 t, %1; cvt.u32.u64 %0, t; }" : "=r"(a) : "l"(p));
    return a;
}

#define LDMX4(r0,r1,r2,r3,addr) \
    asm volatile("ldmatrix.sync.aligned.m8n8.x4.shared.b16 {%0,%1,%2,%3}, [%4];" \
        : "=r"(r0),"=r"(r1),"=r"(r2),"=r"(r3) : "r"(addr))
#define LDMX4T(r0,r1,r2,r3,addr) \
    asm volatile("ldmatrix.sync.aligned.m8n8.x4.trans.shared.b16 {%0,%1,%2,%3}, [%4];" \
        : "=r"(r0),"=r"(r1),"=r"(r2),"=r"(r3) : "r"(addr))

#define MMAH(c0,c1,c2,c3,a0,a1,a2,a3,b0,b1) \
    asm volatile("mma.sync.aligned.m16n8k16.row.col.f32.f16.f16.f32 " \
        "{%0,%1,%2,%3}, {%4,%5,%6,%7}, {%8,%9}, {%0,%1,%2,%3};" \
        : "+f"(c0),"+f"(c1),"+f"(c2),"+f"(c3) \
        : "r"(a0),"r"(a1),"r"(a2),"r"(a3), "r"(b0),"r"(b1))

#define CPASYNC(dst,src,sz) \
    asm volatile("cp.async.cg.shared.global [%0], [%1], 16, %2;" :: "r"(dst), "l"(src), "r"(sz))
#define CPCOMMIT() asm volatile("cp.async.commit_group;")
#define CPWAIT(n)  asm volatile("cp.async.wait_group %0;" :: "n"(n))

// ========== fp16 GEMM: C = A * B^T ; 128x256 tile, 64x64 warp tile, K-chunk 128 ==========
// mode: 0 fp32 out, 1 fp32 += res, 3 silu->fp16, 4 atomic MoE combine,
//       5 paired silu, 7 plain atomicAdd into C
#define ROWB 272
#define STAGE_BYTES (384*ROWB)
#define NSTAGE 2
#define MM16_SMEM (NSTAGE*STAGE_BYTES)

__global__ void __launch_bounds__(256,1) mm16(
    const __half* __restrict__ Ah, const __half* __restrict__ Bh,
    float* __restrict__ C, const float* __restrict__ res,
    __half* __restrict__ Cp16,
    int M, int N, int K, int lda, int ldb, int ldc, int mode,
    const int* __restrict__ counts, const int* __restrict__ offs,
    const int* __restrict__ rows,
    const int* __restrict__ omap, const float* __restrict__ wsl,
    long long bStrideE)
{
    extern __shared__ __align__(16) char dsm[];
    __shared__ int rsrc[128];
    uint32_t ub = smem_u32(dsm);
    int tid = threadIdx.x, wid = tid >> 5, lane = tid & 31;
    int e = blockIdx.z;

    int Mloc = M, rowOff = 0;
    const __half* Bp = Bh;
    if (counts){ Mloc = counts[e]; rowOff = offs[e]; Bp = Bh + (long long)e*bStrideE; }
    int m0 = blockIdx.y * 128;
    if (m0 >= Mloc) return;
    int n0 = blockIdx.x * 256;

    for (int i = tid; i < 128; i += 256){
        int gr = m0 + i;
        rsrc[i] = (gr < Mloc) ? (rows ? rows[rowOff + gr] : (counts ? rowOff + gr : gr)) : -1;
    }
    __syncthreads();

    int r0 = tid >> 3, part = tid & 7;
    uint32_t dbase = (uint32_t)(r0*ROWB + part*16);
    const __half* ap[4]; int asz[4];
    #pragma unroll
    for (int i = 0; i < 4; i++){
        int s = rsrc[r0 + 32*i];
        asz[i] = (s >= 0) ? 16 : 0;
        ap[i] = Ah + (long long)((s >= 0) ? s : 0)*lda + part*8;
    }
    const __half* bb = Bp + (long long)(n0 + r0)*ldb + part*8;
    long long str32 = 32ll*ldb;

#define MM16_ISSUE(stg, kc) do { \
    uint32_t dd = ub + (stg)*STAGE_BYTES + dbase; int ko = (kc)*128; \
    _Pragma("unroll") \
    for (int i = 0; i < 4; i++){ \
        CPASYNC(dd + 32*i*ROWB,       ap[i]+ko,    asz[i]); \
        CPASYNC(dd + 32*i*ROWB + 128, ap[i]+ko+64, asz[i]); \
    } \
    _Pragma("unroll") \
    for (int i = 0; i < 8; i++){ \
        CPASYNC(dd+(128+32*i)*ROWB,       bb + i*str32 + ko,    16); \
        CPASYNC(dd+(128+32*i)*ROWB + 128, bb + i*str32 + ko+64, 16); \
    } \
    CPCOMMIT(); } while(0)

    float acc[4][8][4];
    #pragma unroll
    for (int i=0;i<4;i++) for (int j=0;j<8;j++) for (int f=0;f<4;f++) acc[i][j][f]=0.f;

    int wm = (wid >> 2) * 64, wn = (wid & 3) * 64;
    int lrow = lane & 15, lsel = (lane >> 4) * 8;
    int nk = K >> 7;

    MM16_ISSUE(0, 0);
    for (int kc = 0; kc < nk; kc++){
        CPWAIT(0);
        __syncthreads();
        if (kc + 1 < nk) MM16_ISSUE((kc+1)&1, kc+1);
        uint32_t us = ub + (kc & 1)*STAGE_BYTES;
        #pragma unroll
        for (int ks = 0; ks < 8; ks++){
            int kofs2 = (ks*16 + lsel)*2;
            uint32_t ah[4][4], bh[4][4];
            #pragma unroll
            for (int mt = 0; mt < 4; mt++){
                uint32_t ad = us + (uint32_t)((wm + mt*16 + lrow)*ROWB) + kofs2;
                LDMX4(ah[mt][0],ah[mt][1],ah[mt][2],ah[mt][3], ad);
            }
            #pragma unroll
            for (int j = 0; j < 4; j++){
                uint32_t bd = us + (uint32_t)((128 + wn + j*16 + lrow)*ROWB) + kofs2;
                LDMX4(bh[j][0],bh[j][1],bh[j][2],bh[j][3], bd);
            }
            #pragma unroll
            for (int mt = 0; mt < 4; mt++){
                #pragma unroll
                for (int j = 0; j < 4; j++){
                    float* c0 = acc[mt][2*j];
                    float* c1 = acc[mt][2*j+1];
                    MMAH(c0[0],c0[1],c0[2],c0[3], ah[mt][0],ah[mt][1],ah[mt][2],ah[mt][3], bh[j][0],bh[j][2]);
                    MMAH(c1[0],c1[1],c1[2],c1[3], ah[mt][0],ah[mt][1],ah[mt][2],ah[mt][3], bh[j][1],bh[j][3]);
                }
            }
        }
    }

    int rbase = lane >> 2, cbase = (lane & 3) * 2;

    if (mode == 5){
        float* stage = (float*)dsm;
        __syncthreads();
        if ((wid & 3) >= 2){
            int cb = wn - 128;
            #pragma unroll
            for (int mt = 0; mt < 4; mt++)
                #pragma unroll
                for (int nt = 0; nt < 8; nt++)
                    #pragma unroll
                    for (int half = 0; half < 2; half++){
                        int lm = wm + mt*16 + rbase + half*8;
                        int c = cb + nt*8 + cbase;
                        stage[lm*132 + c]   = acc[mt][nt][2*half];
                        stage[lm*132 + c+1] = acc[mt][nt][2*half+1];
                    }
        }
        __syncthreads();
        if ((wid & 3) < 2){
            int n0h = blockIdx.x * 128;
            #pragma unroll
            for (int mt = 0; mt < 4; mt++)
                #pragma unroll
                for (int nt = 0; nt < 8; nt++)
                    #pragma unroll
                    for (int half = 0; half < 2; half++){
                        int lm = wm + mt*16 + rbase + half*8;
                        int c = wn + nt*8 + cbase;
                        float a1x = acc[mt][nt][2*half];
                        float a1y = acc[mt][nt][2*half+1];
                        float a2x = stage[lm*132 + c];
                        float a2y = stage[lm*132 + c+1];
                        float ox = a1x/(1.f+expf(-a1x))*a2x;
                        float oy = a1y/(1.f+expf(-a1y))*a2y;
                        long long ci = (long long)(m0 + lm)*ldc + n0h + c;
                        *(__half2*)(Cp16 + ci) = __floats2half2_rn(ox, oy);
                    }
        }
        return;
    }

    #pragma unroll
    for (int mt = 0; mt < 4; mt++){
        #pragma unroll
        for (int nt = 0; nt < 8; nt++){
            int gn = n0 + wn + nt*8 + cbase;
            #pragma unroll
            for (int half = 0; half < 2; half++){
                int gm = m0 + wm + mt*16 + rbase + half*8;
                if (gm >= Mloc) continue;
                float v0 = acc[mt][nt][2*half];
                float v1 = acc[mt][nt][2*half+1];
                long long ci = (long long)(rowOff + gm)*ldc + gn;
                if (mode == 1){
                    v0 += res[ci]; v1 += res[ci+1];
                    *(float2*)(C + ci) = make_float2(v0, v1);
                } else if (mode == 3){
                    v0 = v0 / (1.f + expf(-v0));
                    v1 = v1 / (1.f + expf(-v1));
                    *(__half2*)(Cp16 + ci) = __floats2half2_rn(v0, v1);
                } else if (mode == 4){
                    int slot = rowOff + gm;
                    int t = omap[slot];
                    float w = wsl[slot];
                    long long co = (long long)t*ldc + gn;
                    atomicAdd(&C[co],   w*v0);
                    atomicAdd(&C[co+1], w*v1);
                } else if (mode == 7){
                    atomicAdd(&C[ci],   v0);
                    atomicAdd(&C[ci+1], v1);
                } else {
                    *(float2*)(C + ci) = make_float2(v0, v1);
                }
            }
        }
    }
}

// ===== fused flash attention: 2 KV tiles per stage, 2-stage ring (4 barriers) =====
#define FSTR 72
#define KVHALF (128*FSTR*2)         // 18432
#define KVSTG2 (4*KVHALF)           // 2 K tiles + 2 V tiles per stage
#define FLASH_SMEM (KVHALF + 2*KVSTG2)   // 18432 + 147456 = 165888

__global__ void __launch_bounds__(256,1) flash_attn(
    const __half* __restrict__ qh, const __half* __restrict__ kh,
    const __half* __restrict__ vh, const float* __restrict__ mask,
    __half* __restrict__ oh)
{
    extern __shared__ __align__(16) char fsm[];
    __half* sQ = (__half*)fsm;
    uint32_t uQ = smem_u32(fsm);
    uint32_t ukv0 = uQ + KVHALF;

    int tid = threadIdx.x, wid = tid >> 5, lane = tid & 31;
    int bh_ = blockIdx.y, b = bh_ >> 4, h = bh_ & 15;
    int q0 = blockIdx.x * 128;
    long long tb = (long long)b * LL;
    int crow = tid >> 1, chalf = (tid & 1) * 32;

    // issue KV tiles 2it and 2it+1 into stage it&1
#define FLASH_ISSUE2(it) do { \
    uint32_t sb_ = ukv0 + ((it) & 1)*KVSTG2 + (uint32_t)(crow*144 + chalf*2); \
    _Pragma("unroll") \
    for (int p_ = 0; p_ < 2; p_++){ \
        long long g_ = (tb + (2*(it)+p_)*128 + crow)*DIMM + h*HD + chalf; \
        uint32_t dk_ = sb_ + p_*2*KVHALF; \
        const __half* ks_ = kh + g_; const __half* vs_ = vh + g_; \
        CPASYNC(dk_,    ks_,    16); CPASYNC(dk_+16, ks_+8,  16); \
        CPASYNC(dk_+32, ks_+16, 16); CPASYNC(dk_+48, ks_+24, 16); \
        uint32_t dv_ = dk_ + KVHALF; \
        CPASYNC(dv_,    vs_,    16); CPASYNC(dv_+16, vs_+8,  16); \
        CPASYNC(dv_+32, vs_+16, 16); CPASYNC(dv_+48, vs_+24, 16); \
    } \
    CPCOMMIT(); } while(0)

    {
        long long g = (tb + q0 + crow)*DIMM + h*HD + chalf;
        uint4* d0 = (uint4*)&sQ[crow*FSTR + chalf];
        const uint4* s0 = (const uint4*)(qh + g);
        #pragma unroll
        for (int i = 0; i < 4; i++) d0[i] = s0[i];
    }
    FLASH_ISSUE2(0);
    __syncthreads();

    int lr = lane & 15, ls = (lane >> 4) * 8;
    uint32_t aq[4][4];
    #pragma unroll
    for (int kc = 0; kc < 4; kc++){
        uint32_t ad = uQ + 2u*((wid*16 + lr)*FSTR + kc*16 + ls);
        LDMX4(aq[kc][0],aq[kc][1],aq[kc][2],aq[kc][3], ad);
    }

    float oacc[8][4];
    #pragma unroll
    for (int i=0;i<8;i++) for (int j=0;j<4;j++) oacc[i][j]=0.f;
    float m0r = -1e30f, m1r = -1e30f, l0r = 0.f, l1r = 0.f;

    const float* mp0 = mask + (long long)(q0 + wid*16 + (lane>>2))*LL;
    const float* mp1 = mp0 + 8*LL;
    const float SC  = 0.125f * 1.44269504f;
    const float L2E = 1.44269504f;

    for (int it = 0; it < 4; it++){
        CPWAIT(0);
        __syncthreads();
        if (it + 1 < 4) FLASH_ISSUE2(it + 1);
        #pragma unroll
        for (int pass = 0; pass < 2; pass++){
            int jt = 2*it + pass;
            uint32_t uK = ukv0 + (it & 1)*KVSTG2 + pass*2*KVHALF;
            uint32_t uV = uK + KVHALF;

            float s[16][4];
            #pragma unroll
            for (int i=0;i<16;i++) for (int j=0;j<4;j++) s[i][j]=0.f;

            #pragma unroll
            for (int kc = 0; kc < 4; kc++){
                #pragma unroll
                for (int np = 0; np < 8; np++){
                    uint32_t bk[4];
                    uint32_t ad = uK + 2u*((np*16 + lr)*FSTR + kc*16 + ls);
                    LDMX4(bk[0],bk[1],bk[2],bk[3], ad);
                    float* c0 = s[2*np]; float* c1 = s[2*np+1];
                    MMAH(c0[0],c0[1],c0[2],c0[3], aq[kc][0],aq[kc][1],aq[kc][2],aq[kc][3], bk[0],bk[2]);
                    MMAH(c1[0],c1[1],c1[2],c1[3], aq[kc][0],aq[kc][1],aq[kc][2],aq[kc][3], bk[1],bk[3]);
                }
            }

            float mx0 = -1e30f, mx1 = -1e30f;
            #pragma unroll
            for (int nt = 0; nt < 16; nt++){
                int colb = jt*128 + nt*8 + (lane&3)*2;
                float2 mm0 = *(const float2*)(mp0 + colb);
                float2 mm1 = *(const float2*)(mp1 + colb);
                s[nt][0] = fmaf(s[nt][0], SC, mm0.x*L2E);
                s[nt][1] = fmaf(s[nt][1], SC, mm0.y*L2E);
                s[nt][2] = fmaf(s[nt][2], SC, mm1.x*L2E);
                s[nt][3] = fmaf(s[nt][3], SC, mm1.y*L2E);
                mx0 = fmaxf(mx0, fmaxf(s[nt][0], s[nt][1]));
                mx1 = fmaxf(mx1, fmaxf(s[nt][2], s[nt][3]));
            }
            mx0 = fmaxf(mx0, __shfl_xor_sync(0xffffffffu, mx0, 1));
            mx0 = fmaxf(mx0, __shfl_xor_sync(0xffffffffu, mx0, 2));
            mx1 = fmaxf(mx1, __shfl_xor_sync(0xffffffffu, mx1, 1));
            mx1 = fmaxf(mx1, __shfl_xor_sync(0xffffffffu, mx1, 2));

            float nm0 = fmaxf(m0r, mx0), nm1 = fmaxf(m1r, mx1);
            float al0 = exp2f(m0r - nm0), al1 = exp2f(m1r - nm1);
            m0r = nm0; m1r = nm1;

            float rs0 = 0.f, rs1 = 0.f;
            #pragma unroll
            for (int nt = 0; nt < 16; nt++){
                s[nt][0] = exp2f(s[nt][0] - nm0);
                s[nt][1] = exp2f(s[nt][1] - nm0);
                s[nt][2] = exp2f(s[nt][2] - nm1);
                s[nt][3] = exp2f(s[nt][3] - nm1);
                rs0 += s[nt][0] + s[nt][1];
                rs1 += s[nt][2] + s[nt][3];
            }
            rs0 += __shfl_xor_sync(0xffffffffu, rs0, 1);
            rs0 += __shfl_xor_sync(0xffffffffu, rs0, 2);
            rs1 += __shfl_xor_sync(0xffffffffu, rs1, 1);
            rs1 += __shfl_xor_sync(0xffffffffu, rs1, 2);
            l0r = l0r*al0 + rs0;
            l1r = l1r*al1 + rs1;
            #pragma unroll
            for (int dt = 0; dt < 8; dt++){
                oacc[dt][0] *= al0; oacc[dt][1] *= al0;
                oacc[dt][2] *= al1; oacc[dt][3] *= al1;
            }

            #pragma unroll
            for (int kc2 = 0; kc2 < 8; kc2++){
                uint32_t pa[4];
                {
                    __half2 h0 = __floats2half2_rn(s[2*kc2][0],   s[2*kc2][1]);
                    __half2 h1 = __floats2half2_rn(s[2*kc2][2],   s[2*kc2][3]);
                    __half2 h2 = __floats2half2_rn(s[2*kc2+1][0], s[2*kc2+1][1]);
                    __half2 h3 = __floats2half2_rn(s[2*kc2+1][2], s[2*kc2+1][3]);
                    pa[0]=*(uint32_t*)&h0; pa[1]=*(uint32_t*)&h1; pa[2]=*(uint32_t*)&h2; pa[3]=*(uint32_t*)&h3;
                }
                #pragma unroll
                for (int dt = 0; dt < 4; dt++){
                    uint32_t bv[4];
                    uint32_t ad = uV + 2u*((kc2*16 + lr)*FSTR + dt*16 + ls);
                    LDMX4T(bv[0],bv[1],bv[2],bv[3], ad);
                    float* o0 = oacc[2*dt]; float* o1 = oacc[2*dt+1];
                    MMAH(o0[0],o0[1],o0[2],o0[3], pa[0],pa[1],pa[2],pa[3], bv[0],bv[1]);
                    MMAH(o1[0],o1[1],o1[2],o1[3], pa[0],pa[1],pa[2],pa[3], bv[2],bv[3]);
                }
            }
        }
    }

    float i0 = 1.f / l0r, i1 = 1.f / l1r;
    long long r0 = tb + q0 + wid*16 + (lane>>2);
    #pragma unroll
    for (int dt = 0; dt < 8; dt++){
        long long g0 = r0*DIMM + h*HD + dt*8 + (lane&3)*2;
        long long g1 = g0 + 8*DIMM;
        *(__half2*)(oh + g0) = __floats2half2_rn(oacc[dt][0]*i0, oacc[dt][1]*i0);
        *(__half2*)(oh + g1) = __floats2half2_rn(oacc[dt][2]*i1, oacc[dt][3]*i1);
    }
}

// ---------------- misc kernels ----------------
__device__ __forceinline__ float warpReduceSum(float v){
    #pragma unroll
    for (int o=16;o;o>>=1) v += __shfl_xor_sync(0xffffffffu, v, o);
    return v;
}
__device__ float blockReduceSum(float v){
    __shared__ float sh[33];
    int lane = threadIdx.x & 31, wid = threadIdx.x >> 5;
    __syncthreads();
    v = warpReduceSum(v);
    if (lane==0) sh[wid] = v;
    __syncthreads();
    int nw = blockDim.x >> 5;
    float r = (threadIdx.x < nw) ? sh[threadIdx.x] : 0.f;
    if (wid==0){ r = warpReduceSum(r); if (lane==0) sh[32] = r; }
    __syncthreads();
    return sh[32];
}

__global__ void convAll(const float* __restrict__ wq, const float* __restrict__ wk,
                        const float* __restrict__ wv, const float* __restrict__ wo,
                        const float* __restrict__ s1, const float* __restrict__ s2,
                        const float* __restrict__ s3, const float* __restrict__ fc1,
                        const float* __restrict__ fc2, __half* __restrict__ o){
    long long i = ((long long)blockIdx.x*256 + threadIdx.x)*8;
    if (i >= 26*WSEG) return;
    const float* src; long long off; long long dst = i;
    if      (i <  1*WSEG){ src = wq;  off = i; }
    else if (i <  2*WSEG){ src = wk;  off = i -  1*WSEG; }
    else if (i <  3*WSEG){ src = wv;  off = i -  2*WSEG; }
    else if (i <  4*WSEG){ src = wo;  off = i -  3*WSEG; }
    else if (i <  8*WSEG){
        long long o12 = i - 4*WSEG;
        int is2 = (o12 >= 2*WSEG);
        long long o2 = is2 ? o12 - 2*WSEG : o12;
        src = is2 ? s2 : s1; off = o2;
        int r = (int)(o2 >> 10), c = (int)(o2 & 1023);
        int j = r >> 7, rl = r & 127;
        dst = 4*WSEG + (((long long)(j*256 + is2*128 + rl)) << 10) + c;
    }
    else if (i < 10*WSEG){ src = s3;  off = i -  8*WSEG; }
    else if (i < 18*WSEG){ src = fc1; off = i - 10*WSEG; }
    else                 { src = fc2; off = i - 18*WSEG; }
    float4 a = *(const float4*)(src + off);
    float4 b = *(const float4*)(src + off + 4);
    __half2 h0 = __floats2half2_rn(a.x, a.y);
    __half2 h1 = __floats2half2_rn(a.z, a.w);
    __half2 h2 = __floats2half2_rn(b.x, b.y);
    __half2 h3 = __floats2half2_rn(b.z, b.w);
    uint4 pk;
    pk.x = *(uint32_t*)&h0; pk.y = *(uint32_t*)&h1;
    pk.z = *(uint32_t*)&h2; pk.w = *(uint32_t*)&h3;
    *(uint4*)(o + dst) = pk;
}

__global__ void __launch_bounds__(256) rmsnorm16(const float* __restrict__ x,
        const float* __restrict__ w, float* __restrict__ outf,
        __half* __restrict__ o16){
    long long row = blockIdx.x;
    float4 xv = ((const float4*)(x + row*DIMM))[threadIdx.x];
    float ss = xv.x*xv.x + xv.y*xv.y + xv.z*xv.z + xv.w*xv.w;
    float tot = blockReduceSum(ss);
    float scale = rsqrtf(tot * (1.0f/DIMM) + 1e-5f);
    float4 wv = ((const float4*)w)[threadIdx.x];
    float4 o;
    o.x = xv.x*scale*wv.x; o.y = xv.y*scale*wv.y;
    o.z = xv.z*scale*wv.z; o.w = xv.w*scale*wv.w;
    long long i = row*DIMM + threadIdx.x*4;
    if (outf) *(float4*)(outf + i) = o;
    __half2 h01 = __floats2half2_rn(o.x, o.y);
    __half2 h23 = __floats2half2_rn(o.z, o.w);
    *(uint2*)(o16 + i) = make_uint2(*(uint32_t*)&h01, *(uint32_t*)&h23);
}

__global__ void ropeConv(const float* __restrict__ qkv,
                         __half* __restrict__ q16, __half* __restrict__ k16,
                         __half* __restrict__ v16){
    int idx = blockIdx.x*blockDim.x + threadIdx.x;
    if (idx >= NTOK*NHEADS*(HD/2)) return;
    int j = idx & 31;
    int h = (idx >> 5) & 15;
    int t = idx >> 9;
    int l = t & (LL-1);
    long long bsrc = (long long)t*3072 + h*HD;
    long long bdst = (long long)t*DIMM + h*HD;
    float inv = powf(10000.f, -(float)j * (1.f/32.f));
    float ang = (float)l * inv;
    float sn, cs; sincosf(ang, &sn, &cs);
    float a = qkv[bsrc+j], b = qkv[bsrc+32+j];
    q16[bdst+j]    = __float2half_rn(a*cs - b*sn);
    q16[bdst+32+j] = __float2half_rn(a*sn + b*cs);
    a = qkv[bsrc+1024+j]; b = qkv[bsrc+1024+32+j];
    k16[bdst+j]    = __float2half_rn(a*cs - b*sn);
    k16[bdst+32+j] = __float2half_rn(a*sn + b*cs);
    v16[bdst+j]    = __float2half_rn(qkv[bsrc+2048+j]);
    v16[bdst+32+j] = __float2half_rn(qkv[bsrc+2048+32+j]);
}

// out = h  (initialize for atomic accumulation)
__global__ void copyOut(const float* __restrict__ h, float* __restrict__ out){
    long long i = ((long long)blockIdx.x*256 + threadIdx.x)*4;
    if (i >= (long long)NTOK*DIMM) return;
    *(float4*)(out + i) = *(const float4*)(h + i);
}

__global__ void __launch_bounds__(256) gate_topk(const float* __restrict__ xf,
                                                 const float* __restrict__ gw,
                                                 int* __restrict__ topi, float* __restrict__ topw,
                                                 int* __restrict__ counts){
    int t = blockIdx.x;
    int tid = threadIdx.x;
    float4 xv = ((const float4*)(xf + (long long)t*DIMM))[tid];
    float acc[16];
    #pragma unroll
    for (int e = 0; e < 16; e++){
        float4 g = ((const float4*)(gw + (long long)e*DIMM))[tid];
        acc[e] = xv.x*g.x + xv.y*g.y + xv.z*g.z + xv.w*g.w;
    }
    #pragma unroll
    for (int e = 0; e < 16; e++) acc[e] = warpReduceSum(acc[e]);
    __shared__ float wr[8][16];
    __shared__ float lg[16];
    int lane = tid & 31, wid = tid >> 5;
    if (lane == 0){
        #pragma unroll
        for (int e = 0; e < 16; e++) wr[wid][e] = acc[e];
    }
    __syncthreads();
    if (tid < 16){
        float s = 0.f;
        #pragma unroll
        for (int w = 0; w < 8; w++) s += wr[w][tid];
        lg[tid] = s;
    }
    __syncthreads();
    if (tid == 0){
        float l0 = -3.0e38f; int i0 = 0;
        for (int e = 0; e < 16; e++) if (lg[e] > l0){ l0 = lg[e]; i0 = e; }
        float l1 = -3.0e38f; int i1 = 0;
        for (int e = 0; e < 16; e++) if (e != i0 && lg[e] > l1){ l1 = lg[e]; i1 = e; }
        float w1 = expf(l1 - l0);
        float sden = 1.f + w1;
        topi[2*t] = i0; topi[2*t+1] = i1;
        topw[2*t] = 1.f / sden; topw[2*t+1] = w1 / sden;
        atomicAdd(&counts[i0], 1);
        atomicAdd(&counts[i1], 1);
    }
}

__global__ void zero_counts(int* counts){
    if (threadIdx.x < NE) counts[threadIdx.x] = 0;
}
__global__ void scan_kernel(const int* __restrict__ counts, int* __restrict__ offs,
                            int* __restrict__ cursor){
    if (threadIdx.x == 0){
        int s = 0;
        for (int e = 0; e < NE; e++){ offs[e] = s; s += counts[e]; cursor[e] = 0; }
    }
}
__global__ void scatter_kernel(const int* __restrict__ topi, int* __restrict__ cursor,
                               const int* __restrict__ offs, const float* __restrict__ topw,
                               int* __restrict__ order, float* __restrict__ wslot){
    int t = blockIdx.x*blockDim.x + threadIdx.x;
    if (t >= NTOK) return;
    #pragma unroll
    for (int k2 = 0; k2 < 2; k2++){
        int e = topi[2*t+k2];
        int pos = atomicAdd(&cursor[e], 1);
        int slot = offs[e] + pos;
        order[slot] = t;
        wslot[slot] = topw[2*t+k2];
    }
}

// ---------------- host launcher ----------------
extern "C" void kernel_launch(void* const* d_in, const int* in_sizes, int n_in,
                              void* d_out, int out_size){
    const float* x    = (const float*)d_in[0];
    const float* mask = (const float*)d_in[1];
    const float* wq   = (const float*)d_in[2];
    const float* wk   = (const float*)d_in[3];
    const float* wv   = (const float*)d_in[4];
    const float* wo   = (const float*)d_in[5];
    const float* n1   = (const float*)d_in[6];
    const float* n2   = (const float*)d_in[7];
    const float* gw   = (const float*)d_in[8];
    const float* fc1  = (const float*)d_in[9];
    const float* fc2  = (const float*)d_in[10];
    const float* s1   = (const float*)d_in[11];
    const float* s2   = (const float*)d_in[12];
    const float* s3   = (const float*)d_in[13];
    float* out = (float*)d_out;

    void *p;
    cudaGetSymbolAddress(&p, g_qkv);    float* qkv    = (float*)p;
    cudaGetSymbolAddress(&p, g_h);      float* hbuf   = (float*)p;
    cudaGetSymbolAddress(&p, g_xf);     float* xf     = (float*)p;
    cudaGetSymbolAddress(&p, g_wh);     __half* wh   = (__half*)p;
    cudaGetSymbolAddress(&p, g_hn16);   __half* hn16 = (__half*)p;
    cudaGetSymbolAddress(&p, g_q16);    __half* q16  = (__half*)p;
    cudaGetSymbolAddress(&p, g_k16);    __half* k16  = (__half*)p;
    cudaGetSymbolAddress(&p, g_v16);    __half* v16  = (__half*)p;
    cudaGetSymbolAddress(&p, g_a16);    __half* a16  = (__half*)p;
    cudaGetSymbolAddress(&p, g_x16);    __half* x16  = (__half*)p;
    cudaGetSymbolAddress(&p, g_ta16);   __half* ta16 = (__half*)p;
    cudaGetSymbolAddress(&p, g_e16);    __half* e16  = (__half*)p;
    cudaGetSymbolAddress(&p, g_topi);   int*   topi   = (int*)p;
    cudaGetSymbolAddress(&p, g_topw);   float* topw   = (float*)p;
    cudaGetSymbolAddress(&p, g_counts); int*   counts = (int*)p;
    cudaGetSymbolAddress(&p, g_cursor); int*   cursor = (int*)p;
    cudaGetSymbolAddress(&p, g_offs);   int*   offs   = (int*)p;
    cudaGetSymbolAddress(&p, g_order);  int*   order  = (int*)p;
    cudaGetSymbolAddress(&p, g_wslot);  float* wslot  = (float*)p;

    cudaFuncSetAttribute(mm16, cudaFuncAttributeMaxDynamicSharedMemorySize, MM16_SMEM);
    cudaFuncSetAttribute(flash_attn, cudaFuncAttributeMaxDynamicSharedMemorySize, FLASH_SMEM);

    __half* W_QKV = wh;
    __half* W_O   = wh +  3*WSEG;
    __half* W_S12 = wh +  4*WSEG;
    __half* W_S3  = wh +  8*WSEG;
    __half* W_FC1 = wh + 10*WSEG;
    __half* W_FC2 = wh + 18*WSEG;

    cudaStream_t sB;
    cudaStreamCreateWithFlags(&sB, cudaStreamNonBlocking);
    cudaEvent_t eFork, eW, eX, eF2;
    cudaEventCreateWithFlags(&eFork, cudaEventDisableTiming);
    cudaEventCreateWithFlags(&eW,    cudaEventDisableTiming);
    cudaEventCreateWithFlags(&eX,    cudaEventDisableTiming);
    cudaEventCreateWithFlags(&eF2,   cudaEventDisableTiming);

    // fork: convAll on sB, rmsnorm1 on main
    cudaEventRecord(eFork, 0);
    cudaStreamWaitEvent(sB, eFork, 0);
    convAll<<<(int)(26*WSEG/2048), 256, 0, sB>>>(wq, wk, wv, wo, s1, s2, s3, fc1, fc2, wh);
    cudaEventRecord(eW, sB);
    rmsnorm16<<<NTOK, 256>>>(x, n1, nullptr, hn16);
    cudaStreamWaitEvent(0, eW, 0);

    // QKV
    mm16<<<dim3(12,32,1),256,MM16_SMEM>>>(hn16, W_QKV, qkv, nullptr, nullptr,
        NTOK, 3*DIMM, DIMM, DIMM, DIMM, 3*DIMM, 0, nullptr, nullptr, nullptr, nullptr, nullptr, 0);
    ropeConv<<<(NTOK*NHEADS*32)/256, 256>>>(qkv, q16, k16, v16);
    flash_attn<<<dim3(8,64),256,FLASH_SMEM>>>(q16, k16, v16, mask, a16);
    mm16<<<dim3(4,32,1),256,MM16_SMEM>>>(a16, W_O, hbuf, x, nullptr,
        NTOK, DIMM, DIMM, DIMM, DIMM, DIMM, 1, nullptr, nullptr, nullptr, nullptr, nullptr, 0);
    // out = h (base for atomic accumulation by S3 and expert fc2)
    copyOut<<<(NTOK*DIMM)/1024, 256>>>(hbuf, out);
    rmsnorm16<<<NTOK, 256>>>(hbuf, n2, xf, x16);
    cudaEventRecord(eX, 0);

    // branch B: routing + expert fc1 + expert fc2 (atomic into out)
    cudaStreamWaitEvent(sB, eX, 0);
    zero_counts<<<1,32,0,sB>>>(counts);
    gate_topk<<<NTOK,256,0,sB>>>(xf, gw, topi, topw, counts);
    scan_kernel<<<1,1,0,sB>>>(counts, offs, cursor);
    scatter_kernel<<<NTOK/256,256,0,sB>>>(topi, cursor, offs, topw, order, wslot);
    mm16<<<dim3(2,64,NE),256,MM16_SMEM,sB>>>(x16, W_FC1, nullptr, nullptr, e16,
        0, HID, DIMM, DIMM, DIMM, HID, 3, counts, offs, order, nullptr, nullptr, (long long)HID*DIMM);
    mm16<<<dim3(4,64,NE),256,MM16_SMEM,sB>>>(e16, W_FC2, out, nullptr, nullptr,
        0, DIMM, HID, HID, HID, DIMM, 4, counts, offs, nullptr, order, wslot, (long long)DIMM*HID);
    cudaEventRecord(eF2, sB);

    // main: shared expert (fused silu) + S3 atomically into out (concurrent with fc2)
    mm16<<<dim3(16,32,1),256,MM16_SMEM>>>(x16, W_S12, nullptr, nullptr, ta16,
        NTOK, 2*NSHARED, DIMM, DIMM, DIMM, NSHARED, 5, nullptr, nullptr, nullptr, nullptr, nullptr, 0);
    mm16<<<dim3(4,32,1),256,MM16_SMEM>>>(ta16, W_S3, out, nullptr, nullptr,
        NTOK, DIMM, NSHARED, NSHARED, NSHARED, DIMM, 7, nullptr, nullptr, nullptr, nullptr, nullptr, 0);

    // join
    cudaStreamWaitEvent(0, eF2, 0);
}

// round 17
// speedup vs baseline: 1.0602x; 1.0150x over previous
#include <cuda_runtime.h>
#include <cuda_fp16.h>
#include <math.h>
#include <stdint.h>

#define BB 4
#define LL 1024
#define DIMM 1024
#define NHEADS 16
#define HD 64
#define NTOK (BB*LL)
#define HID 512
#define NE 16
#define NSHARED 2048
#define NSLOTS (NTOK*2)

// ---------------- scratch ----------------
__device__ float g_qkv[NTOK*3*DIMM];
__device__ float g_h[NTOK*DIMM];
__device__ float g_xf[NTOK*DIMM];
// fp16 buffers
#define WSEG 1048576ll
__device__ __half g_wh[26*WSEG];
__device__ __half g_hn16[NTOK*DIMM];
__device__ __half g_q16[NTOK*DIMM];
__device__ __half g_k16[NTOK*DIMM];
__device__ __half g_v16[NTOK*DIMM];
__device__ __half g_a16[NTOK*DIMM];
__device__ __half g_x16[NTOK*DIMM];
__device__ __half g_ta16[NTOK*NSHARED];
__device__ __half g_e16[NSLOTS*HID];
// routing
__device__ int   g_topi[NSLOTS];
__device__ float g_topw[NSLOTS];
__device__ int   g_counts[NE];
__device__ int   g_cursor[NE];
__device__ int   g_offs[NE];
__device__ int   g_order[NSLOTS];
__device__ float g_wslot[NSLOTS];

__device__ __forceinline__ uint32_t smem_u32(const void* p){
    uint32_t a;
    asm("{ .reg .u64 t; cvta.to.shared.u64 t, %1; cvt.u32.u64 %0, t; }" : "=r"(a) : "l"(p));
    return a;
}

#define LDMX4(r0,r1,r2,r3,addr) \
    asm volatile("ldmatrix.sync.aligned.m8n8.x4.shared.b16 {%0,%1,%2,%3}, [%4];" \
        : "=r"(r0),"=r"(r1),"=r"(r2),"=r"(r3) : "r"(addr))
#define LDMX4T(r0,r1,r2,r3,addr) \
    asm volatile("ldmatrix.sync.aligned.m8n8.x4.trans.shared.b16 {%0,%1,%2,%3}, [%4];" \
        : "=r"(r0),"=r"(r1),"=r"(r2),"=r"(r3) : "r"(addr))

#define MMAH(c0,c1,c2,c3,a0,a1,a2,a3,b0,b1) \
    asm volatile("mma.sync.aligned.m16n8k16.row.col.f32.f16.f16.f32 " \
        "{%0,%1,%2,%3}, {%4,%5,%6,%7}, {%8,%9}, {%0,%1,%2,%3};" \
        : "+f"(c0),"+f"(c1),"+f"(c2),"+f"(c3) \
        : "r"(a0),"r"(a1),"r"(a2),"r"(a3), "r"(b0),"r"(b1))

#define CPASYNC(dst,src,sz) \
    asm volatile("cp.async.cg.shared.global [%0], [%1], 16, %2;" :: "r"(dst), "l"(src), "r"(sz))
#define CPCOMMIT() asm volatile("cp.async.commit_group;")
#define CPWAIT(n)  asm volatile("cp.async.wait_group %0;" :: "n"(n))

// ========== fp16 GEMM: C = A * B^T ; 128x256 tile, 64x64 warp tile, K-chunk 128 ==========
// mode: 0 fp32 out, 1 fp32 += res, 3 silu->fp16, 4 atomic MoE combine,
//       5 paired silu, 7 plain atomicAdd into C, 8 res add -> C and C2
#define ROWB 272
#define STAGE_BYTES (384*ROWB)
#define NSTAGE 2
#define MM16_SMEM (NSTAGE*STAGE_BYTES)

__global__ void __launch_bounds__(256,1) mm16(
    const __half* __restrict__ Ah, const __half* __restrict__ Bh,
    float* __restrict__ C, const float* __restrict__ res,
    __half* __restrict__ Cp16, float* __restrict__ C2,
    int M, int N, int K, int lda, int ldb, int ldc, int mode,
    const int* __restrict__ counts, const int* __restrict__ offs,
    const int* __restrict__ rows,
    const int* __restrict__ omap, const float* __restrict__ wsl,
    long long bStrideE)
{
    extern __shared__ __align__(16) char dsm[];
    __shared__ int rsrc[128];
    uint32_t ub = smem_u32(dsm);
    int tid = threadIdx.x, wid = tid >> 5, lane = tid & 31;
    int e = blockIdx.z;

    int Mloc = M, rowOff = 0;
    const __half* Bp = Bh;
    if (counts){ Mloc = counts[e]; rowOff = offs[e]; Bp = Bh + (long long)e*bStrideE; }
    int m0 = blockIdx.y * 128;
    if (m0 >= Mloc) return;
    int n0 = blockIdx.x * 256;

    for (int i = tid; i < 128; i += 256){
        int gr = m0 + i;
        rsrc[i] = (gr < Mloc) ? (rows ? rows[rowOff + gr] : (counts ? rowOff + gr : gr)) : -1;
    }
    __syncthreads();

    int r0 = tid >> 3, part = tid & 7;
    uint32_t dbase = (uint32_t)(r0*ROWB + part*16);
    const __half* ap[4]; int asz[4];
    #pragma unroll
    for (int i = 0; i < 4; i++){
        int s = rsrc[r0 + 32*i];
        asz[i] = (s >= 0) ? 16 : 0;
        ap[i] = Ah + (long long)((s >= 0) ? s : 0)*lda + part*8;
    }
    const __half* bb = Bp + (long long)(n0 + r0)*ldb + part*8;
    long long str32 = 32ll*ldb;

#define MM16_ISSUE(stg, kc) do { \
    uint32_t dd = ub + (stg)*STAGE_BYTES + dbase; int ko = (kc)*128; \
    _Pragma("unroll") \
    for (int i = 0; i < 4; i++){ \
        CPASYNC(dd + 32*i*ROWB,       ap[i]+ko,    asz[i]); \
        CPASYNC(dd + 32*i*ROWB + 128, ap[i]+ko+64, asz[i]); \
    } \
    _Pragma("unroll") \
    for (int i = 0; i < 8; i++){ \
        CPASYNC(dd+(128+32*i)*ROWB,       bb + i*str32 + ko,    16); \
        CPASYNC(dd+(128+32*i)*ROWB + 128, bb + i*str32 + ko+64, 16); \
    } \
    CPCOMMIT(); } while(0)

    float acc[4][8][4];
    #pragma unroll
    for (int i=0;i<4;i++) for (int j=0;j<8;j++) for (int f=0;f<4;f++) acc[i][j][f]=0.f;

    int wm = (wid >> 2) * 64, wn = (wid & 3) * 64;
    int lrow = lane & 15, lsel = (lane >> 4) * 8;
    int nk = K >> 7;

    MM16_ISSUE(0, 0);
    for (int kc = 0; kc < nk; kc++){
        CPWAIT(0);
        __syncthreads();
        if (kc + 1 < nk) MM16_ISSUE((kc+1)&1, kc+1);
        uint32_t us = ub + (kc & 1)*STAGE_BYTES;
        #pragma unroll
        for (int ks = 0; ks < 8; ks++){
            int kofs2 = (ks*16 + lsel)*2;
            uint32_t ah[4][4], bh[4][4];
            #pragma unroll
            for (int mt = 0; mt < 4; mt++){
                uint32_t ad = us + (uint32_t)((wm + mt*16 + lrow)*ROWB) + kofs2;
                LDMX4(ah[mt][0],ah[mt][1],ah[mt][2],ah[mt][3], ad);
            }
            #pragma unroll
            for (int j = 0; j < 4; j++){
                uint32_t bd = us + (uint32_t)((128 + wn + j*16 + lrow)*ROWB) + kofs2;
                LDMX4(bh[j][0],bh[j][1],bh[j][2],bh[j][3], bd);
            }
            #pragma unroll
            for (int mt = 0; mt < 4; mt++){
                #pragma unroll
                for (int j = 0; j < 4; j++){
                    float* c0 = acc[mt][2*j];
                    float* c1 = acc[mt][2*j+1];
                    MMAH(c0[0],c0[1],c0[2],c0[3], ah[mt][0],ah[mt][1],ah[mt][2],ah[mt][3], bh[j][0],bh[j][2]);
                    MMAH(c1[0],c1[1],c1[2],c1[3], ah[mt][0],ah[mt][1],ah[mt][2],ah[mt][3], bh[j][1],bh[j][3]);
                }
            }
        }
    }

    int rbase = lane >> 2, cbase = (lane & 3) * 2;

    if (mode == 5){
        float* stage = (float*)dsm;
        __syncthreads();
        if ((wid & 3) >= 2){
            int cb = wn - 128;
            #pragma unroll
            for (int mt = 0; mt < 4; mt++)
                #pragma unroll
                for (int nt = 0; nt < 8; nt++)
                    #pragma unroll
                    for (int half = 0; half < 2; half++){
                        int lm = wm + mt*16 + rbase + half*8;
                        int c = cb + nt*8 + cbase;
                        stage[lm*132 + c]   = acc[mt][nt][2*half];
                        stage[lm*132 + c+1] = acc[mt][nt][2*half+1];
                    }
        }
        __syncthreads();
        if ((wid & 3) < 2){
            int n0h = blockIdx.x * 128;
            #pragma unroll
            for (int mt = 0; mt < 4; mt++)
                #pragma unroll
                for (int nt = 0; nt < 8; nt++)
                    #pragma unroll
                    for (int half = 0; half < 2; half++){
                        int lm = wm + mt*16 + rbase + half*8;
                        int c = wn + nt*8 + cbase;
                        float a1x = acc[mt][nt][2*half];
                        float a1y = acc[mt][nt][2*half+1];
                        float a2x = stage[lm*132 + c];
                        float a2y = stage[lm*132 + c+1];
                        float ox = a1x/(1.f+expf(-a1x))*a2x;
                        float oy = a1y/(1.f+expf(-a1y))*a2y;
                        long long ci = (long long)(m0 + lm)*ldc + n0h + c;
                        *(__half2*)(Cp16 + ci) = __floats2half2_rn(ox, oy);
                    }
        }
        return;
    }

    #pragma unroll
    for (int mt = 0; mt < 4; mt++){
        #pragma unroll
        for (int nt = 0; nt < 8; nt++){
            int gn = n0 + wn + nt*8 + cbase;
            #pragma unroll
            for (int half = 0; half < 2; half++){
                int gm = m0 + wm + mt*16 + rbase + half*8;
                if (gm >= Mloc) continue;
                float v0 = acc[mt][nt][2*half];
                float v1 = acc[mt][nt][2*half+1];
                long long ci = (long long)(rowOff + gm)*ldc + gn;
                if (mode == 1){
                    v0 += res[ci]; v1 += res[ci+1];
                    *(float2*)(C + ci) = make_float2(v0, v1);
                } else if (mode == 8){
                    v0 += res[ci]; v1 += res[ci+1];
                    float2 o = make_float2(v0, v1);
                    *(float2*)(C + ci)  = o;
                    *(float2*)(C2 + ci) = o;
                } else if (mode == 3){
                    v0 = v0 / (1.f + expf(-v0));
                    v1 = v1 / (1.f + expf(-v1));
                    *(__half2*)(Cp16 + ci) = __floats2half2_rn(v0, v1);
                } else if (mode == 4){
                    int slot = rowOff + gm;
                    int t = omap[slot];
                    float w = wsl[slot];
                    long long co = (long long)t*ldc + gn;
                    atomicAdd(&C[co],   w*v0);
                    atomicAdd(&C[co+1], w*v1);
                } else if (mode == 7){
                    atomicAdd(&C[ci],   v0);
                    atomicAdd(&C[ci+1], v1);
                } else {
                    *(float2*)(C + ci) = make_float2(v0, v1);
                }
            }
        }
    }
}

// ===== fused flash attention: 2 KV tiles per stage, 2-stage ring =====
#define FSTR 72
#define KVHALF (128*FSTR*2)
#define KVSTG2 (4*KVHALF)
#define FLASH_SMEM (KVHALF + 2*KVSTG2)

__global__ void __launch_bounds__(256,1) flash_attn(
    const __half* __restrict__ qh, const __half* __restrict__ kh,
    const __half* __restrict__ vh, const float* __restrict__ mask,
    __half* __restrict__ oh)
{
    extern __shared__ __align__(16) char fsm[];
    __half* sQ = (__half*)fsm;
    uint32_t uQ = smem_u32(fsm);
    uint32_t ukv0 = uQ + KVHALF;

    int tid = threadIdx.x, wid = tid >> 5, lane = tid & 31;
    int bh_ = blockIdx.y, b = bh_ >> 4, h = bh_ & 15;
    int q0 = blockIdx.x * 128;
    long long tb = (long long)b * LL;
    int crow = tid >> 1, chalf = (tid & 1) * 32;

#define FLASH_ISSUE2(it) do { \
    uint32_t sb_ = ukv0 + ((it) & 1)*KVSTG2 + (uint32_t)(crow*144 + chalf*2); \
    _Pragma("unroll") \
    for (int p_ = 0; p_ < 2; p_++){ \
        long long g_ = (tb + (2*(it)+p_)*128 + crow)*DIMM + h*HD + chalf; \
        uint32_t dk_ = sb_ + p_*2*KVHALF; \
        const __half* ks_ = kh + g_; const __half* vs_ = vh + g_; \
        CPASYNC(dk_,    ks_,    16); CPASYNC(dk_+16, ks_+8,  16); \
        CPASYNC(dk_+32, ks_+16, 16); CPASYNC(dk_+48, ks_+24, 16); \
        uint32_t dv_ = dk_ + KVHALF; \
        CPASYNC(dv_,    vs_,    16); CPASYNC(dv_+16, vs_+8,  16); \
        CPASYNC(dv_+32, vs_+16, 16); CPASYNC(dv_+48, vs_+24, 16); \
    } \
    CPCOMMIT(); } while(0)

    {
        long long g = (tb + q0 + crow)*DIMM + h*HD + chalf;
        uint4* d0 = (uint4*)&sQ[crow*FSTR + chalf];
        const uint4* s0 = (const uint4*)(qh + g);
        #pragma unroll
        for (int i = 0; i < 4; i++) d0[i] = s0[i];
    }
    FLASH_ISSUE2(0);
    __syncthreads();

    int lr = lane & 15, ls = (lane >> 4) * 8;
    uint32_t aq[4][4];
    #pragma unroll
    for (int kc = 0; kc < 4; kc++){
        uint32_t ad = uQ + 2u*((wid*16 + lr)*FSTR + kc*16 + ls);
        LDMX4(aq[kc][0],aq[kc][1],aq[kc][2],aq[kc][3], ad);
    }

    float oacc[8][4];
    #pragma unroll
    for (int i=0;i<8;i++) for (int j=0;j<4;j++) oacc[i][j]=0.f;
    float m0r = -1e30f, m1r = -1e30f, l0r = 0.f, l1r = 0.f;

    const float* mp0 = mask + (long long)(q0 + wid*16 + (lane>>2))*LL;
    const float* mp1 = mp0 + 8*LL;
    const float SC  = 0.125f * 1.44269504f;
    const float L2E = 1.44269504f;

    for (int it = 0; it < 4; it++){
        CPWAIT(0);
        __syncthreads();
        if (it + 1 < 4) FLASH_ISSUE2(it + 1);
        #pragma unroll
        for (int pass = 0; pass < 2; pass++){
            int jt = 2*it + pass;
            uint32_t uK = ukv0 + (it & 1)*KVSTG2 + pass*2*KVHALF;
            uint32_t uV = uK + KVHALF;

            float s[16][4];
            #pragma unroll
            for (int i=0;i<16;i++) for (int j=0;j<4;j++) s[i][j]=0.f;

            #pragma unroll
            for (int kc = 0; kc < 4; kc++){
                #pragma unroll
                for (int np = 0; np < 8; np++){
                    uint32_t bk[4];
                    uint32_t ad = uK + 2u*((np*16 + lr)*FSTR + kc*16 + ls);
                    LDMX4(bk[0],bk[1],bk[2],bk[3], ad);
                    float* c0 = s[2*np]; float* c1 = s[2*np+1];
                    MMAH(c0[0],c0[1],c0[2],c0[3], aq[kc][0],aq[kc][1],aq[kc][2],aq[kc][3], bk[0],bk[2]);
                    MMAH(c1[0],c1[1],c1[2],c1[3], aq[kc][0],aq[kc][1],aq[kc][2],aq[kc][3], bk[1],bk[3]);
                }
            }

            float mx0 = -1e30f, mx1 = -1e30f;
            #pragma unroll
            for (int nt = 0; nt < 16; nt++){
                int colb = jt*128 + nt*8 + (lane&3)*2;
                float2 mm0 = *(const float2*)(mp0 + colb);
                float2 mm1 = *(const float2*)(mp1 + colb);
                s[nt][0] = fmaf(s[nt][0], SC, mm0.x*L2E);
                s[nt][1] = fmaf(s[nt][1], SC, mm0.y*L2E);
                s[nt][2] = fmaf(s[nt][2], SC, mm1.x*L2E);
                s[nt][3] = fmaf(s[nt][3], SC, mm1.y*L2E);
                mx0 = fmaxf(mx0, fmaxf(s[nt][0], s[nt][1]));
                mx1 = fmaxf(mx1, fmaxf(s[nt][2], s[nt][3]));
            }
            mx0 = fmaxf(mx0, __shfl_xor_sync(0xffffffffu, mx0, 1));
            mx0 = fmaxf(mx0, __shfl_xor_sync(0xffffffffu, mx0, 2));
            mx1 = fmaxf(mx1, __shfl_xor_sync(0xffffffffu, mx1, 1));
            mx1 = fmaxf(mx1, __shfl_xor_sync(0xffffffffu, mx1, 2));

            float nm0 = fmaxf(m0r, mx0), nm1 = fmaxf(m1r, mx1);
            float al0 = exp2f(m0r - nm0), al1 = exp2f(m1r - nm1);
            m0r = nm0; m1r = nm1;

            float rs0 = 0.f, rs1 = 0.f;
            #pragma unroll
            for (int nt = 0; nt < 16; nt++){
                s[nt][0] = exp2f(s[nt][0] - nm0);
                s[nt][1] = exp2f(s[nt][1] - nm0);
                s[nt][2] = exp2f(s[nt][2] - nm1);
                s[nt][3] = exp2f(s[nt][3] - nm1);
                rs0 += s[nt][0] + s[nt][1];
                rs1 += s[nt][2] + s[nt][3];
            }
            rs0 += __shfl_xor_sync(0xffffffffu, rs0, 1);
            rs0 += __shfl_xor_sync(0xffffffffu, rs0, 2);
            rs1 += __shfl_xor_sync(0xffffffffu, rs1, 1);
            rs1 += __shfl_xor_sync(0xffffffffu, rs1, 2);
            l0r = l0r*al0 + rs0;
            l1r = l1r*al1 + rs1;
            #pragma unroll
            for (int dt = 0; dt < 8; dt++){
                oacc[dt][0] *= al0; oacc[dt][1] *= al0;
                oacc[dt][2] *= al1; oacc[dt][3] *= al1;
            }

            #pragma unroll
            for (int kc2 = 0; kc2 < 8; kc2++){
                uint32_t pa[4];
                {
                    __half2 h0 = __floats2half2_rn(s[2*kc2][0],   s[2*kc2][1]);
                    __half2 h1 = __floats2half2_rn(s[2*kc2][2],   s[2*kc2][3]);
                    __half2 h2 = __floats2half2_rn(s[2*kc2+1][0], s[2*kc2+1][1]);
                    __half2 h3 = __floats2half2_rn(s[2*kc2+1][2], s[2*kc2+1][3]);
                    pa[0]=*(uint32_t*)&h0; pa[1]=*(uint32_t*)&h1; pa[2]=*(uint32_t*)&h2; pa[3]=*(uint32_t*)&h3;
                }
                #pragma unroll
                for (int dt = 0; dt < 4; dt++){
                    uint32_t bv[4];
                    uint32_t ad = uV + 2u*((kc2*16 + lr)*FSTR + dt*16 + ls);
                    LDMX4T(bv[0],bv[1],bv[2],bv[3], ad);
                    float* o0 = oacc[2*dt]; float* o1 = oacc[2*dt+1];
                    MMAH(o0[0],o0[1],o0[2],o0[3], pa[0],pa[1],pa[2],pa[3], bv[0],bv[1]);
                    MMAH(o1[0],o1[1],o1[2],o1[3], pa[0],pa[1],pa[2],pa[3], bv[2],bv[3]);
                }
            }
        }
    }

    float i0 = 1.f / l0r, i1 = 1.f / l1r;
    long long r0 = tb + q0 + wid*16 + (lane>>2);
    #pragma unroll
    for (int dt = 0; dt < 8; dt++){
        long long g0 = r0*DIMM + h*HD + dt*8 + (lane&3)*2;
        long long g1 = g0 + 8*DIMM;
        *(__half2*)(oh + g0) = __floats2half2_rn(oacc[dt][0]*i0, oacc[dt][1]*i0);
        *(__half2*)(oh + g1) = __floats2half2_rn(oacc[dt][2]*i1, oacc[dt][3]*i1);
    }
}

// ---------------- misc kernels ----------------
__device__ __forceinline__ float warpReduceSum(float v){
    #pragma unroll
    for (int o=16;o;o>>=1) v += __shfl_xor_sync(0xffffffffu, v, o);
    return v;
}
__device__ float blockReduceSum(float v){
    __shared__ float sh[33];
    int lane = threadIdx.x & 31, wid = threadIdx.x >> 5;
    __syncthreads();
    v = warpReduceSum(v);
    if (lane==0) sh[wid] = v;
    __syncthreads();
    int nw = blockDim.x >> 5;
    float r = (threadIdx.x < nw) ? sh[threadIdx.x] : 0.f;
    if (wid==0){ r = warpReduceSum(r); if (lane==0) sh[32] = r; }
    __syncthreads();
    return sh[32];
}

__device__ __forceinline__ void convPack(const float* src, __half* dst){
    float4 a = *(const float4*)src;
    float4 b = *(const float4*)(src + 4);
    __half2 h0 = __floats2half2_rn(a.x, a.y);
    __half2 h1 = __floats2half2_rn(a.z, a.w);
    __half2 h2 = __floats2half2_rn(b.x, b.y);
    __half2 h3 = __floats2half2_rn(b.z, b.w);
    uint4 pk;
    pk.x = *(uint32_t*)&h0; pk.y = *(uint32_t*)&h1;
    pk.z = *(uint32_t*)&h2; pk.w = *(uint32_t*)&h3;
    *(uint4*)dst = pk;
}

// attention weights (wq|wk|wv|wo -> segments 0..4)
__global__ void convA(const float* __restrict__ wq, const float* __restrict__ wk,
                      const float* __restrict__ wv, const float* __restrict__ wo,
                      __half* __restrict__ o){
    long long i = ((long long)blockIdx.x*256 + threadIdx.x)*8;
    if (i >= 4*WSEG) return;
    const float* src; long long off;
    if      (i < 1*WSEG){ src = wq; off = i; }
    else if (i < 2*WSEG){ src = wk; off = i - 1*WSEG; }
    else if (i < 3*WSEG){ src = wv; off = i - 2*WSEG; }
    else                { src = wo; off = i - 3*WSEG; }
    convPack(src + off, o + i);
}

// FFN/expert weights (s1/s2 interleaved, s3, fc1, fc2 -> segments 4..26)
__global__ void convB(const float* __restrict__ s1, const float* __restrict__ s2,
                      const float* __restrict__ s3, const float* __restrict__ fc1,
                      const float* __restrict__ fc2, __half* __restrict__ o){
    long long i = 4*WSEG + ((long long)blockIdx.x*256 + threadIdx.x)*8;
    if (i >= 26*WSEG) return;
    const float* src; long long off; long long dst = i;
    if (i < 8*WSEG){
        long long o12 = i - 4*WSEG;
        int is2 = (o12 >= 2*WSEG);
        long long o2 = is2 ? o12 - 2*WSEG : o12;
        src = is2 ? s2 : s1; off = o2;
        int r = (int)(o2 >> 10), c = (int)(o2 & 1023);
        int j = r >> 7, rl = r & 127;
        dst = 4*WSEG + (((long long)(j*256 + is2*128 + rl)) << 10) + c;
    }
    else if (i < 10*WSEG){ src = s3;  off = i -  8*WSEG; }
    else if (i < 18*WSEG){ src = fc1; off = i - 10*WSEG; }
    else                 { src = fc2; off = i - 18*WSEG; }
    convPack(src + off, o + dst);
}

__global__ void __launch_bounds__(256) rmsnorm16(const float* __restrict__ x,
        const float* __restrict__ w, float* __restrict__ outf,
        __half* __restrict__ o16){
    long long row = blockIdx.x;
    float4 xv = ((const float4*)(x + row*DIMM))[threadIdx.x];
    float ss = xv.x*xv.x + xv.y*xv.y + xv.z*xv.z + xv.w*xv.w;
    float tot = blockReduceSum(ss);
    float scale = rsqrtf(tot * (1.0f/DIMM) + 1e-5f);
    float4 wv = ((const float4*)w)[threadIdx.x];
    float4 o;
    o.x = xv.x*scale*wv.x; o.y = xv.y*scale*wv.y;
    o.z = xv.z*scale*wv.z; o.w = xv.w*scale*wv.w;
    long long i = row*DIMM + threadIdx.x*4;
    if (outf) *(float4*)(outf + i) = o;
    __half2 h01 = __floats2half2_rn(o.x, o.y);
    __half2 h23 = __floats2half2_rn(o.z, o.w);
    *(uint2*)(o16 + i) = make_uint2(*(uint32_t*)&h01, *(uint32_t*)&h23);
}

__global__ void ropeConv(const float* __restrict__ qkv,
                         __half* __restrict__ q16, __half* __restrict__ k16,
                         __half* __restrict__ v16){
    int idx = blockIdx.x*blockDim.x + threadIdx.x;
    if (idx >= NTOK*NHEADS*(HD/2)) return;
    int j = idx & 31;
    int h = (idx >> 5) & 15;
    int t = idx >> 9;
    int l = t & (LL-1);
    long long bsrc = (long long)t*3072 + h*HD;
    long long bdst = (long long)t*DIMM + h*HD;
    float inv = powf(10000.f, -(float)j * (1.f/32.f));
    float ang = (float)l * inv;
    float sn, cs; sincosf(ang, &sn, &cs);
    float a = qkv[bsrc+j], b = qkv[bsrc+32+j];
    q16[bdst+j]    = __float2half_rn(a*cs - b*sn);
    q16[bdst+32+j] = __float2half_rn(a*sn + b*cs);
    a = qkv[bsrc+1024+j]; b = qkv[bsrc+1024+32+j];
    k16[bdst+j]    = __float2half_rn(a*cs - b*sn);
    k16[bdst+32+j] = __float2half_rn(a*sn + b*cs);
    v16[bdst+j]    = __float2half_rn(qkv[bsrc+2048+j]);
    v16[bdst+32+j] = __float2half_rn(qkv[bsrc+2048+32+j]);
}

__global__ void __launch_bounds__(256) gate_topk(const float* __restrict__ xf,
                                                 const float* __restrict__ gw,
                                                 int* __restrict__ topi, float* __restrict__ topw,
                                                 int* __restrict__ counts){
    int t = blockIdx.x;
    int tid = threadIdx.x;
    float4 xv = ((const float4*)(xf + (long long)t*DIMM))[tid];
    float acc[16];
    #pragma unroll
    for (int e = 0; e < 16; e++){
        float4 g = ((const float4*)(gw + (long long)e*DIMM))[tid];
        acc[e] = xv.x*g.x + xv.y*g.y + xv.z*g.z + xv.w*g.w;
    }
    #pragma unroll
    for (int e = 0; e < 16; e++) acc[e] = warpReduceSum(acc[e]);
    __shared__ float wr[8][16];
    __shared__ float lg[16];
    int lane = tid & 31, wid = tid >> 5;
    if (lane == 0){
        #pragma unroll
        for (int e = 0; e < 16; e++) wr[wid][e] = acc[e];
    }
    __syncthreads();
    if (tid < 16){
        float s = 0.f;
        #pragma unroll
        for (int w = 0; w < 8; w++) s += wr[w][tid];
        lg[tid] = s;
    }
    __syncthreads();
    if (tid == 0){
        float l0 = -3.0e38f; int i0 = 0;
        for (int e = 0; e < 16; e++) if (lg[e] > l0){ l0 = lg[e]; i0 = e; }
        float l1 = -3.0e38f; int i1 = 0;
        for (int e = 0; e < 16; e++) if (e != i0 && lg[e] > l1){ l1 = lg[e]; i1 = e; }
        float w1 = expf(l1 - l0);
        float sden = 1.f + w1;
        topi[2*t] = i0; topi[2*t+1] = i1;
        topw[2*t] = 1.f / sden; topw[2*t+1] = w1 / sden;
        atomicAdd(&counts[i0], 1);
        atomicAdd(&counts[i1], 1);
    }
}

__global__ void zero_counts(int* counts){
    if (threadIdx.x < NE) counts[threadIdx.x] = 0;
}
__global__ void scan_kernel(const int* __restrict__ counts, int* __restrict__ offs,
                            int* __restrict__ cursor){
    if (threadIdx.x == 0){
        int s = 0;
        for (int e = 0; e < NE; e++){ offs[e] = s; s += counts[e]; cursor[e] = 0; }
    }
}
__global__ void scatter_kernel(const int* __restrict__ topi, int* __restrict__ cursor,
                               const int* __restrict__ offs, const float* __restrict__ topw,
                               int* __restrict__ order, float* __restrict__ wslot){
    int t = blockIdx.x*blockDim.x + threadIdx.x;
    if (t >= NTOK) return;
    #pragma unroll
    for (int k2 = 0; k2 < 2; k2++){
        int e = topi[2*t+k2];
        int pos = atomicAdd(&cursor[e], 1);
        int slot = offs[e] + pos;
        order[slot] = t;
        wslot[slot] = topw[2*t+k2];
    }
}

// ---------------- host launcher ----------------
extern "C" void kernel_launch(void* const* d_in, const int* in_sizes, int n_in,
                              void* d_out, int out_size){
    const float* x    = (const float*)d_in[0];
    const float* mask = (const float*)d_in[1];
    const float* wq   = (const float*)d_in[2];
    const float* wk   = (const float*)d_in[3];
    const float* wv   = (const float*)d_in[4];
    const float* wo   = (const float*)d_in[5];
    const float* n1   = (const float*)d_in[6];
    const float* n2   = (const float*)d_in[7];
    const float* gw   = (const float*)d_in[8];
    const float* fc1  = (const float*)d_in[9];
    const float* fc2  = (const float*)d_in[10];
    const float* s1   = (const float*)d_in[11];
    const float* s2   = (const float*)d_in[12];
    const float* s3   = (const float*)d_in[13];
    float* out = (float*)d_out;

    void *p;
    cudaGetSymbolAddress(&p, g_qkv);    float* qkv    = (float*)p;
    cudaGetSymbolAddress(&p, g_h);      float* hbuf   = (float*)p;
    cudaGetSymbolAddress(&p, g_xf);     float* xf     = (float*)p;
    cudaGetSymbolAddress(&p, g_wh);     __half* wh   = (__half*)p;
    cudaGetSymbolAddress(&p, g_hn16);   __half* hn16 = (__half*)p;
    cudaGetSymbolAddress(&p, g_q16);    __half* q16  = (__half*)p;
    cudaGetSymbolAddress(&p, g_k16);    __half* k16  = (__half*)p;
    cudaGetSymbolAddress(&p, g_v16);    __half* v16  = (__half*)p;
    cudaGetSymbolAddress(&p, g_a16);    __half* a16  = (__half*)p;
    cudaGetSymbolAddress(&p, g_x16);    __half* x16  = (__half*)p;
    cudaGetSymbolAddress(&p, g_ta16);   __half* ta16 = (__half*)p;
    cudaGetSymbolAddress(&p, g_e16);    __half* e16  = (__half*)p;
    cudaGetSymbolAddress(&p, g_topi);   int*   topi   = (int*)p;
    cudaGetSymbolAddress(&p, g_topw);   float* topw   = (float*)p;
    cudaGetSymbolAddress(&p, g_counts); int*   counts = (int*)p;
    cudaGetSymbolAddress(&p, g_cursor); int*   cursor = (int*)p;
    cudaGetSymbolAddress(&p, g_offs);   int*   offs   = (int*)p;
    cudaGetSymbolAddress(&p, g_order);  int*   order  = (int*)p;
    cudaGetSymbolAddress(&p, g_wslot);  float* wslot  = (float*)p;

    cudaFuncSetAttribute(mm16, cudaFuncAttributeMaxDynamicSharedMemorySize, MM16_SMEM);
    cudaFuncSetAttribute(flash_attn, cudaFuncAttributeMaxDynamicSharedMemorySize, FLASH_SMEM);

    __half* W_QKV = wh;
    __half* W_O   = wh +  3*WSEG;
    __half* W_S12 = wh +  4*WSEG;
    __half* W_S3  = wh +  8*WSEG;
    __half* W_FC1 = wh + 10*WSEG;
    __half* W_FC2 = wh + 18*WSEG;

    cudaStream_t sB;
    cudaStreamCreateWithFlags(&sB, cudaStreamNonBlocking);
    cudaEvent_t eFork, eW1, eW2, eX, eF2;
    cudaEventCreateWithFlags(&eFork, cudaEventDisableTiming);
    cudaEventCreateWithFlags(&eW1,   cudaEventDisableTiming);
    cudaEventCreateWithFlags(&eW2,   cudaEventDisableTiming);
    cudaEventCreateWithFlags(&eX,    cudaEventDisableTiming);
    cudaEventCreateWithFlags(&eF2,   cudaEventDisableTiming);

    // fork: convA (attention weights) then convB (FFN weights) on sB; rmsnorm1 on main
    cudaEventRecord(eFork, 0);
    cudaStreamWaitEvent(sB, eFork, 0);
    convA<<<(int)(4*WSEG/2048), 256, 0, sB>>>(wq, wk, wv, wo, wh);
    cudaEventRecord(eW1, sB);
    convB<<<(int)(22*WSEG/2048), 256, 0, sB>>>(s1, s2, s3, fc1, fc2, wh);
    cudaEventRecord(eW2, sB);
    rmsnorm16<<<NTOK, 256>>>(x, n1, nullptr, hn16);
    cudaStreamWaitEvent(0, eW1, 0);     // only attention weights needed for QKV/WO

    // QKV (convB runs concurrently on sB)
    mm16<<<dim3(12,32,1),256,MM16_SMEM>>>(hn16, W_QKV, qkv, nullptr, nullptr, nullptr,
        NTOK, 3*DIMM, DIMM, DIMM, DIMM, 3*DIMM, 0, nullptr, nullptr, nullptr, nullptr, nullptr, 0);
    ropeConv<<<(NTOK*NHEADS*32)/256, 256>>>(qkv, q16, k16, v16);
    flash_attn<<<dim3(8,64),256,FLASH_SMEM>>>(q16, k16, v16, mask, a16);
    // WO: h = x + attn@wo^T, duplicated into out (mode 8)
    mm16<<<dim3(4,32,1),256,MM16_SMEM>>>(a16, W_O, hbuf, x, nullptr, out,
        NTOK, DIMM, DIMM, DIMM, DIMM, DIMM, 8, nullptr, nullptr, nullptr, nullptr, nullptr, 0);
    rmsnorm16<<<NTOK, 256>>>(hbuf, n2, xf, x16);
    cudaEventRecord(eX, 0);

    // branch B: routing + expert fc1 + expert fc2 (atomic into out)
    cudaStreamWaitEvent(sB, eX, 0);
    zero_counts<<<1,32,0,sB>>>(counts);
    gate_topk<<<NTOK,256,0,sB>>>(xf, gw, topi, topw, counts);
    scan_kernel<<<1,1,0,sB>>>(counts, offs, cursor);
    scatter_kernel<<<NTOK/256,256,0,sB>>>(topi, cursor, offs, topw, order, wslot);
    mm16<<<dim3(2,64,NE),256,MM16_SMEM,sB>>>(x16, W_FC1, nullptr, nullptr, e16, nullptr,
        0, HID, DIMM, DIMM, DIMM, HID, 3, counts, offs, order, nullptr, nullptr, (long long)HID*DIMM);
    mm16<<<dim3(4,64,NE),256,MM16_SMEM,sB>>>(e16, W_FC2, out, nullptr, nullptr, nullptr,
        0, DIMM, HID, HID, HID, DIMM, 4, counts, offs, nullptr, order, wslot, (long long)DIMM*HID);
    cudaEventRecord(eF2, sB);

    // main: shared expert (fused silu) + S3 atomically into out (needs FFN weights)
    cudaStreamWaitEvent(0, eW2, 0);
    mm16<<<dim3(16,32,1),256,MM16_SMEM>>>(x16, W_S12, nullptr, nullptr, ta16, nullptr,
        NTOK, 2*NSHARED, DIMM, DIMM, DIMM, NSHARED, 5, nullptr, nullptr, nullptr, nullptr, nullptr, 0);
    mm16<<<dim3(4,32,1),256,MM16_SMEM>>>(ta16, W_S3, out, nullptr, nullptr, nullptr,
        NTOK, DIMM, NSHARED, NSHARED, NSHARED, DIMM, 7, nullptr, nullptr, nullptr, nullptr, nullptr, 0);

    // join
    cudaStreamWaitEvent(0, eF2, 0);
}